// round 1
// baseline (speedup 1.0000x reference)
#include <cuda_runtime.h>
#include <math.h>

// Problem constants
#define BATCH 2
#define SEQ   2048
#define DM    1024
#define NH    16
#define HD    64
#define MTOT  (BATCH*SEQ)   // 4096

static const size_t OUT_ELEMS  = (size_t)BATCH * SEQ * DM;          // 4,194,304
static const size_t ATTN_ELEMS = (size_t)BATCH * NH * SEQ * SEQ;    // 134,217,728

// Device scratch (allocation-free rule: use __device__ globals)
__device__ float g_q  [BATCH*NH*SEQ*HD];
__device__ float g_k  [BATCH*NH*SEQ*HD];
__device__ float g_v  [BATCH*NH*SEQ*HD];
__device__ float g_ctx[BATCH*SEQ*DM];
__device__ float g_attn_scratch[(size_t)BATCH*NH*SEQ*SEQ];  // fallback if attn not part of d_out

// ---------------------------------------------------------------------------
// SGEMM: C[m,n] = sum_k A[m,k] * W[n,k] + bias[n]
// A: MxK row-major, W: NxK row-major (torch Linear weight), both K-contiguous.
// MODE 0: write into [B,H,S,HD] head layout (QKV projections)
// MODE 1: plain row-major [M,N] (ctx @ Wo^T and similar)
// Tiles: 128x128x16, 256 threads, 8x8 per thread.
// ---------------------------------------------------------------------------
template<int MODE>
__global__ void __launch_bounds__(256)
sgemm_tn(const float* __restrict__ A, const float* __restrict__ W,
         const float* __restrict__ bias, float* __restrict__ C,
         int M, int N, int K)
{
    __shared__ float As[16][128];
    __shared__ float Bs[16][128];

    const int tid = threadIdx.x;
    const int m0 = blockIdx.y * 128;
    const int n0 = blockIdx.x * 128;

    const int lr = tid >> 2;          // 0..63
    const int lc = (tid & 3) * 4;     // 0,4,8,12
    const int ty = tid >> 4;          // 0..15
    const int tx = tid & 15;          // 0..15

    float acc[8][8];
#pragma unroll
    for (int i = 0; i < 8; i++)
#pragma unroll
        for (int j = 0; j < 8; j++) acc[i][j] = 0.f;

    for (int k0 = 0; k0 < K; k0 += 16) {
#pragma unroll
        for (int r = 0; r < 128; r += 64) {
            float4 a = *(const float4*)&A[(size_t)(m0 + lr + r) * K + k0 + lc];
            As[lc + 0][lr + r] = a.x;
            As[lc + 1][lr + r] = a.y;
            As[lc + 2][lr + r] = a.z;
            As[lc + 3][lr + r] = a.w;
            float4 b = *(const float4*)&W[(size_t)(n0 + lr + r) * K + k0 + lc];
            Bs[lc + 0][lr + r] = b.x;
            Bs[lc + 1][lr + r] = b.y;
            Bs[lc + 2][lr + r] = b.z;
            Bs[lc + 3][lr + r] = b.w;
        }
        __syncthreads();

#pragma unroll
        for (int kk = 0; kk < 16; kk++) {
            float4 a0 = *(const float4*)&As[kk][ty * 8];
            float4 a1 = *(const float4*)&As[kk][ty * 8 + 4];
            float4 b0 = *(const float4*)&Bs[kk][tx * 8];
            float4 b1 = *(const float4*)&Bs[kk][tx * 8 + 4];
            float av[8] = {a0.x, a0.y, a0.z, a0.w, a1.x, a1.y, a1.z, a1.w};
            float bv[8] = {b0.x, b0.y, b0.z, b0.w, b1.x, b1.y, b1.z, b1.w};
#pragma unroll
            for (int i = 0; i < 8; i++)
#pragma unroll
                for (int j = 0; j < 8; j++)
                    acc[i][j] = fmaf(av[i], bv[j], acc[i][j]);
        }
        __syncthreads();
    }

#pragma unroll
    for (int i = 0; i < 8; i++) {
        int row = m0 + ty * 8 + i;
#pragma unroll
        for (int j = 0; j < 8; j++) {
            int col = n0 + tx * 8 + j;
            float v = acc[i][j] + bias[col];
            if (MODE == 0) {
                int b  = row >> 11;        // row / SEQ
                int s  = row & (SEQ - 1);
                int h  = col >> 6;         // col / HD
                int dd = col & (HD - 1);
                C[(((size_t)(b * NH + h)) * SEQ + s) * HD + dd] = v;
            } else {
                C[(size_t)row * N + col] = v;
            }
        }
    }
}

// ---------------------------------------------------------------------------
// Scores kernel: per (b,h), 64x64 tile of S = (q k^T)/8 ; s += res*sin(s+phase)
// Writes raw modulated scores to attn buffer (normalized later in place).
// ---------------------------------------------------------------------------
__global__ void __launch_bounds__(256)
scores_kernel(const float* __restrict__ q, const float* __restrict__ k,
              const float* __restrict__ res, const float* __restrict__ ph,
              float* __restrict__ attn)
{
    __shared__ float qt[HD][68];   // transposed: qt[d][row]
    __shared__ float kt[HD][68];   // transposed: kt[d][col]

    const int bh = blockIdx.z;
    const int h  = bh & (NH - 1);
    const int i0 = blockIdx.y * 64;
    const int j0 = blockIdx.x * 64;

    const float* qb = q + (size_t)bh * SEQ * HD;
    const float* kb = k + (size_t)bh * SEQ * HD;

    const int tid = threadIdx.x;
    const int row = tid >> 4;          // 0..15
    const int c4  = (tid & 15) * 4;    // 0..60

#pragma unroll
    for (int t = 0; t < 4; t++) {
        int r = row + t * 16;
        float4 a = *(const float4*)&qb[(size_t)(i0 + r) * HD + c4];
        qt[c4 + 0][r] = a.x; qt[c4 + 1][r] = a.y;
        qt[c4 + 2][r] = a.z; qt[c4 + 3][r] = a.w;
        float4 b = *(const float4*)&kb[(size_t)(j0 + r) * HD + c4];
        kt[c4 + 0][r] = b.x; kt[c4 + 1][r] = b.y;
        kt[c4 + 2][r] = b.z; kt[c4 + 3][r] = b.w;
    }
    __syncthreads();

    const int ty = tid >> 4;
    const int tx = tid & 15;

    float acc[4][4];
#pragma unroll
    for (int i = 0; i < 4; i++)
#pragma unroll
        for (int j = 0; j < 4; j++) acc[i][j] = 0.f;

#pragma unroll
    for (int d = 0; d < HD; d++) {
        float4 a = *(const float4*)&qt[d][ty * 4];
        float4 b = *(const float4*)&kt[d][tx * 4];
        float av[4] = {a.x, a.y, a.z, a.w};
        float bv[4] = {b.x, b.y, b.z, b.w};
#pragma unroll
        for (int i = 0; i < 4; i++)
#pragma unroll
            for (int j = 0; j < 4; j++)
                acc[i][j] = fmaf(av[i], bv[j], acc[i][j]);
    }

    const float R = res[h];
    const float P = ph[h];
    float* out = attn + ((size_t)bh * SEQ + i0) * SEQ + j0;

#pragma unroll
    for (int i = 0; i < 4; i++) {
        float4 o;
        float* oo = &o.x;
#pragma unroll
        for (int j = 0; j < 4; j++) {
            float s = acc[i][j] * 0.125f;     // 1/sqrt(64)
            s += R * __sinf(s + P);           // |s| small: MUFU.SIN accurate here
            oo[j] = s;
        }
        *(float4*)&out[(size_t)(ty * 4 + i) * SEQ + tx * 4] = o;
    }
}

// ---------------------------------------------------------------------------
// Row softmax in place: one CTA per row (2048 elements, 8 per thread).
// ---------------------------------------------------------------------------
__device__ __forceinline__ float warpMax(float v) {
#pragma unroll
    for (int o = 16; o; o >>= 1) v = fmaxf(v, __shfl_xor_sync(0xffffffffu, v, o));
    return v;
}
__device__ __forceinline__ float warpSum(float v) {
#pragma unroll
    for (int o = 16; o; o >>= 1) v += __shfl_xor_sync(0xffffffffu, v, o);
    return v;
}

__global__ void __launch_bounds__(256)
softmax_kernel(float* __restrict__ attn)
{
    __shared__ float red[8];
    __shared__ float bval;

    float* p = attn + (size_t)blockIdx.x * SEQ;
    const int tid = threadIdx.x;

    float4 v0 = *(const float4*)&p[tid * 8];
    float4 v1 = *(const float4*)&p[tid * 8 + 4];
    float vals[8] = {v0.x, v0.y, v0.z, v0.w, v1.x, v1.y, v1.z, v1.w};

    float m = vals[0];
#pragma unroll
    for (int i = 1; i < 8; i++) m = fmaxf(m, vals[i]);
    m = warpMax(m);
    if ((tid & 31) == 0) red[tid >> 5] = m;
    __syncthreads();
    if (tid < 32) {
        float x = (tid < 8) ? red[tid] : -1e30f;
        x = warpMax(x);
        if (tid == 0) bval = x;
    }
    __syncthreads();
    m = bval;
    __syncthreads();

    float s = 0.f;
#pragma unroll
    for (int i = 0; i < 8; i++) {
        vals[i] = __expf(vals[i] - m);
        s += vals[i];
    }
    s = warpSum(s);
    if ((tid & 31) == 0) red[tid >> 5] = s;
    __syncthreads();
    if (tid < 32) {
        float x = (tid < 8) ? red[tid] : 0.f;
        x = warpSum(x);
        if (tid == 0) bval = x;
    }
    __syncthreads();
    float inv = 1.f / bval;

    float4 o0 = {vals[0]*inv, vals[1]*inv, vals[2]*inv, vals[3]*inv};
    float4 o1 = {vals[4]*inv, vals[5]*inv, vals[6]*inv, vals[7]*inv};
    *(float4*)&p[tid * 8]     = o0;
    *(float4*)&p[tid * 8 + 4] = o1;
}

// ---------------------------------------------------------------------------
// PV kernel: per (b,h), ctx[b, i, h*64+d] = sum_j attn[i,j] * v[b,h,j,d]
// 64x64 output tile, K-loop over 2048 in chunks of 64.
// ---------------------------------------------------------------------------
__global__ void __launch_bounds__(256)
pv_kernel(const float* __restrict__ attn, const float* __restrict__ v,
          float* __restrict__ ctx)
{
    __shared__ float Pt[64][68];   // transposed: Pt[kk][row]
    __shared__ float Vs[64][68];   // Vs[kk][d]

    const int bh = blockIdx.z;
    const int b  = bh >> 4;
    const int h  = bh & 15;
    const int i0 = blockIdx.x * 64;

    const float* Pb = attn + ((size_t)bh * SEQ + i0) * SEQ;
    const float* Vb = v + (size_t)bh * SEQ * HD;

    const int tid = threadIdx.x;
    const int row = tid >> 4;
    const int c4  = (tid & 15) * 4;
    const int ty  = tid >> 4;
    const int tx  = tid & 15;

    float acc[4][4];
#pragma unroll
    for (int i = 0; i < 4; i++)
#pragma unroll
        for (int j = 0; j < 4; j++) acc[i][j] = 0.f;

    for (int k0 = 0; k0 < SEQ; k0 += 64) {
#pragma unroll
        for (int t = 0; t < 4; t++) {
            int r = row + t * 16;
            float4 a = *(const float4*)&Pb[(size_t)r * SEQ + k0 + c4];
            Pt[c4 + 0][r] = a.x; Pt[c4 + 1][r] = a.y;
            Pt[c4 + 2][r] = a.z; Pt[c4 + 3][r] = a.w;
            float4 vv = *(const float4*)&Vb[(size_t)(k0 + r) * HD + c4];
            *(float4*)&Vs[r][c4] = vv;
        }
        __syncthreads();

#pragma unroll
        for (int kk = 0; kk < 64; kk++) {
            float4 a = *(const float4*)&Pt[kk][ty * 4];
            float4 bb = *(const float4*)&Vs[kk][tx * 4];
            float av[4] = {a.x, a.y, a.z, a.w};
            float bv[4] = {bb.x, bb.y, bb.z, bb.w};
#pragma unroll
            for (int i = 0; i < 4; i++)
#pragma unroll
                for (int j = 0; j < 4; j++)
                    acc[i][j] = fmaf(av[i], bv[j], acc[i][j]);
        }
        __syncthreads();
    }

#pragma unroll
    for (int i = 0; i < 4; i++) {
        float4 o = {acc[i][0], acc[i][1], acc[i][2], acc[i][3]};
        *(float4*)&ctx[((size_t)b * SEQ + i0 + ty * 4 + i) * DM + h * HD + tx * 4] = o;
    }
}

// ---------------------------------------------------------------------------
// Launch
// ---------------------------------------------------------------------------
extern "C" void kernel_launch(void* const* d_in, const int* in_sizes, int n_in,
                              void* d_out, int out_size)
{
    const float* query = (const float*)d_in[0];
    const float* key   = (const float*)d_in[1];
    const float* value = (const float*)d_in[2];
    const float* Wq    = (const float*)d_in[3];
    const float* bq    = (const float*)d_in[4];
    const float* Wk    = (const float*)d_in[5];
    const float* bk    = (const float*)d_in[6];
    const float* Wv    = (const float*)d_in[7];
    const float* bv    = (const float*)d_in[8];
    const float* Wo    = (const float*)d_in[9];
    const float* bo    = (const float*)d_in[10];
    const float* reso  = (const float*)d_in[11];
    const float* phas  = (const float*)d_in[12];

    float *qg, *kg, *vg, *ctx, *scratch;
    cudaGetSymbolAddress((void**)&qg,      g_q);
    cudaGetSymbolAddress((void**)&kg,      g_k);
    cudaGetSymbolAddress((void**)&vg,      g_v);
    cudaGetSymbolAddress((void**)&ctx,     g_ctx);
    cudaGetSymbolAddress((void**)&scratch, g_attn_scratch);

    float* out_ptr = (float*)d_out;
    const bool attn_in_out = ((size_t)out_size >= OUT_ELEMS + ATTN_ELEMS);
    float* attn_ptr = attn_in_out ? (out_ptr + OUT_ELEMS) : scratch;

    // 1) QKV projections (write directly into [B,H,S,HD])
    dim3 gP(DM / 128, MTOT / 128);   // (8, 32)
    sgemm_tn<0><<<gP, 256>>>(query, Wq, bq, qg, MTOT, DM, DM);
    sgemm_tn<0><<<gP, 256>>>(key,   Wk, bk, kg, MTOT, DM, DM);
    sgemm_tn<0><<<gP, 256>>>(value, Wv, bv, vg, MTOT, DM, DM);

    // 2) Scores + harmonic modulation -> attn buffer (raw)
    dim3 gS(SEQ / 64, SEQ / 64, BATCH * NH);   // (32, 32, 32)
    scores_kernel<<<gS, 256>>>(qg, kg, reso, phas, attn_ptr);

    // 3) Row softmax in place
    softmax_kernel<<<BATCH * NH * SEQ, 256>>>(attn_ptr);

    // 4) attn @ V -> ctx in [B,S,D]
    dim3 gV(SEQ / 64, 1, BATCH * NH);          // (32, 1, 32)
    pv_kernel<<<gV, 256>>>(attn_ptr, vg, ctx);

    // 5) Output projection -> d_out[0 : OUT_ELEMS]
    sgemm_tn<1><<<gP, 256>>>(ctx, Wo, bo, out_ptr, MTOT, DM, DM);
}

// round 2
// speedup vs baseline: 1.0708x; 1.0708x over previous
#include <cuda_runtime.h>
#include <math.h>

// Problem constants
#define BATCH 2
#define SEQ   2048
#define DM    1024
#define NH    16
#define HD    64
#define MTOT  (BATCH*SEQ)   // 4096
#define JT    (SEQ/128)     // 16 j-tiles per row

static const size_t OUT_ELEMS  = (size_t)BATCH * SEQ * DM;          // 4,194,304
static const size_t ATTN_ELEMS = (size_t)BATCH * NH * SEQ * SEQ;    // 134,217,728

// Device scratch (allocation-free rule: __device__ globals)
__device__ float g_q  [BATCH*NH*SEQ*HD];
__device__ float g_k  [BATCH*NH*SEQ*HD];
__device__ float g_v  [BATCH*NH*SEQ*HD];
__device__ float g_ctx[BATCH*SEQ*DM];
__device__ float g_zpart[(size_t)BATCH*NH*JT*SEQ];                  // 4MB partial row sums
__device__ float g_attn_scratch[(size_t)BATCH*NH*SEQ*SEQ];          // fallback

// ---------------------------------------------------------------------------
// SGEMM: C[m,n] = sum_k A[m,k] * W[n,k] + bias[n]
// MODE 0: QKV fused (blockIdx.z selects input/weight/output, head layout out)
// MODE 1: plain row-major [M,N] output (O projection)
// 128x128x16 tiles, 256 threads, 8x8 per thread.
// ---------------------------------------------------------------------------
template<int MODE>
__global__ void __launch_bounds__(256)
sgemm_tn(const float* __restrict__ A0, const float* __restrict__ A1, const float* __restrict__ A2,
         const float* __restrict__ W0, const float* __restrict__ W1, const float* __restrict__ W2,
         const float* __restrict__ b0, const float* __restrict__ b1, const float* __restrict__ b2,
         float* __restrict__ C0, float* __restrict__ C1, float* __restrict__ C2,
         int M, int N, int K)
{
    const float* A; const float* W; const float* bias; float* C;
    if (MODE == 0) {
        int z = blockIdx.z;
        A    = (z == 0) ? A0 : (z == 1) ? A1 : A2;
        W    = (z == 0) ? W0 : (z == 1) ? W1 : W2;
        bias = (z == 0) ? b0 : (z == 1) ? b1 : b2;
        C    = (z == 0) ? C0 : (z == 1) ? C1 : C2;
    } else {
        A = A0; W = W0; bias = b0; C = C0;
    }

    __shared__ float As[16][128];
    __shared__ float Bs[16][128];

    const int tid = threadIdx.x;
    const int m0 = blockIdx.y * 128;
    const int n0 = blockIdx.x * 128;

    const int lr = tid >> 2;          // 0..63
    const int lc = (tid & 3) * 4;     // 0,4,8,12
    const int ty = tid >> 4;          // 0..15
    const int tx = tid & 15;          // 0..15

    float acc[8][8];
#pragma unroll
    for (int i = 0; i < 8; i++)
#pragma unroll
        for (int j = 0; j < 8; j++) acc[i][j] = 0.f;

    for (int k0 = 0; k0 < K; k0 += 16) {
#pragma unroll
        for (int r = 0; r < 128; r += 64) {
            float4 a = *(const float4*)&A[(size_t)(m0 + lr + r) * K + k0 + lc];
            As[lc + 0][lr + r] = a.x;
            As[lc + 1][lr + r] = a.y;
            As[lc + 2][lr + r] = a.z;
            As[lc + 3][lr + r] = a.w;
            float4 b = *(const float4*)&W[(size_t)(n0 + lr + r) * K + k0 + lc];
            Bs[lc + 0][lr + r] = b.x;
            Bs[lc + 1][lr + r] = b.y;
            Bs[lc + 2][lr + r] = b.z;
            Bs[lc + 3][lr + r] = b.w;
        }
        __syncthreads();

#pragma unroll
        for (int kk = 0; kk < 16; kk++) {
            float4 a0 = *(const float4*)&As[kk][ty * 8];
            float4 a1 = *(const float4*)&As[kk][ty * 8 + 4];
            float4 bq0 = *(const float4*)&Bs[kk][tx * 8];
            float4 bq1 = *(const float4*)&Bs[kk][tx * 8 + 4];
            float av[8] = {a0.x, a0.y, a0.z, a0.w, a1.x, a1.y, a1.z, a1.w};
            float bv[8] = {bq0.x, bq0.y, bq0.z, bq0.w, bq1.x, bq1.y, bq1.z, bq1.w};
#pragma unroll
            for (int i = 0; i < 8; i++)
#pragma unroll
                for (int j = 0; j < 8; j++)
                    acc[i][j] = fmaf(av[i], bv[j], acc[i][j]);
        }
        __syncthreads();
    }

#pragma unroll
    for (int i = 0; i < 8; i++) {
        int row = m0 + ty * 8 + i;
#pragma unroll
        for (int j = 0; j < 8; j++) {
            int col = n0 + tx * 8 + j;
            float v = acc[i][j] + bias[col];
            if (MODE == 0) {
                int b  = row >> 11;        // row / SEQ
                int s  = row & (SEQ - 1);
                int h  = col >> 6;         // col / HD
                int dd = col & (HD - 1);
                C[(((size_t)(b * NH + h)) * SEQ + s) * HD + dd] = v;
            } else {
                C[(size_t)row * N + col] = v;
            }
        }
    }
}

// ---------------------------------------------------------------------------
// Scores: per (b,h), 128x128 tile of S = (q k^T)/8 ; s += res*sin(s+phase);
// writes UNNORMALIZED exp(s) to attn, per-(row, j-tile) partial sums to zpart.
// 8x8 per thread, K=64 fully resident in smem (no k-loop).
// ---------------------------------------------------------------------------
__global__ void __launch_bounds__(256)
scores_kernel(const float* __restrict__ q, const float* __restrict__ k,
              const float* __restrict__ res, const float* __restrict__ ph,
              float* __restrict__ attn, float* __restrict__ zpart)
{
    __shared__ float qt[HD][132];   // qt[d][row]
    __shared__ float kt[HD][132];   // kt[d][col]

    const int bh = blockIdx.z;
    const int h  = bh & (NH - 1);
    const int i0 = blockIdx.y * 128;
    const int j0 = blockIdx.x * 128;

    const float* qb = q + (size_t)bh * SEQ * HD;
    const float* kb = k + (size_t)bh * SEQ * HD;

    const int tid = threadIdx.x;
    const int rb  = tid >> 4;          // 0..15
    const int c4  = (tid & 15) * 4;    // 0..60

#pragma unroll
    for (int t = 0; t < 8; t++) {
        int r = rb + t * 16;           // 0..127
        float4 a = *(const float4*)&qb[(size_t)(i0 + r) * HD + c4];
        qt[c4 + 0][r] = a.x; qt[c4 + 1][r] = a.y;
        qt[c4 + 2][r] = a.z; qt[c4 + 3][r] = a.w;
        float4 b = *(const float4*)&kb[(size_t)(j0 + r) * HD + c4];
        kt[c4 + 0][r] = b.x; kt[c4 + 1][r] = b.y;
        kt[c4 + 2][r] = b.z; kt[c4 + 3][r] = b.w;
    }
    __syncthreads();

    const int ty = tid >> 4;
    const int tx = tid & 15;

    float acc[8][8];
#pragma unroll
    for (int i = 0; i < 8; i++)
#pragma unroll
        for (int j = 0; j < 8; j++) acc[i][j] = 0.f;

#pragma unroll
    for (int d = 0; d < HD; d++) {
        float4 a0 = *(const float4*)&qt[d][ty * 8];
        float4 a1 = *(const float4*)&qt[d][ty * 8 + 4];
        float4 b0 = *(const float4*)&kt[d][tx * 8];
        float4 b1 = *(const float4*)&kt[d][tx * 8 + 4];
        float av[8] = {a0.x, a0.y, a0.z, a0.w, a1.x, a1.y, a1.z, a1.w};
        float bv[8] = {b0.x, b0.y, b0.z, b0.w, b1.x, b1.y, b1.z, b1.w};
#pragma unroll
        for (int i = 0; i < 8; i++)
#pragma unroll
            for (int j = 0; j < 8; j++)
                acc[i][j] = fmaf(av[i], bv[j], acc[i][j]);
    }

    const float R = res[h];
    const float P = ph[h];
    float rowsum[8];
#pragma unroll
    for (int i = 0; i < 8; i++) rowsum[i] = 0.f;

#pragma unroll
    for (int i = 0; i < 8; i++) {
        float4 o0, o1;
        float* oo = &o0.x;
#pragma unroll
        for (int j = 0; j < 8; j++) {
            float s = acc[i][j] * 0.125f;        // 1/sqrt(64)
            s += R * __sinf(s + P);
            float e = __expf(s);                 // |s| <~ 7 -> exp safe, no max needed
            rowsum[i] += e;
            if (j < 4) (&o0.x)[j] = e; else (&o1.x)[j - 4] = e;
        }
        (void)oo;
        float* orow = attn + ((size_t)bh * SEQ + i0 + ty * 8 + i) * SEQ + j0;
        *(float4*)&orow[tx * 8]     = o0;
        *(float4*)&orow[tx * 8 + 4] = o1;
    }

    // per-row partial-sum reduction across tx
    __syncthreads();                 // done with qt: reuse as reduction buffer
    float* red = (float*)qt;         // [128][16]
#pragma unroll
    for (int i = 0; i < 8; i++) red[(ty * 8 + i) * 16 + tx] = rowsum[i];
    __syncthreads();
    if (tid < 128) {
        float s = 0.f;
#pragma unroll
        for (int t = 0; t < 16; t++) s += red[tid * 16 + t];
        zpart[((size_t)bh * JT + blockIdx.x) * SEQ + i0 + tid] = s;
    }
}

// ---------------------------------------------------------------------------
// Fused normalize + PV: per (b,h, 128-row block):
//   Z[row] = sum of 16 partials; attn[row,:] = e/Z (written back);
//   ctx[b, row, h*64+d] = sum_j attn[row,j] * v[b,h,j,d]
// 128x64 output tile, 8x4 per thread, k-chunks of 64.
// ---------------------------------------------------------------------------
__global__ void __launch_bounds__(256)
pv_fused_kernel(float* __restrict__ attn, const float* __restrict__ v,
                const float* __restrict__ zpart, float* __restrict__ ctx)
{
    __shared__ float Pt[64][132];   // Pt[kk][row]
    __shared__ float Vs[64][68];    // Vs[kk][d]
    __shared__ float invZ[128];

    const int bh = blockIdx.y;
    const int b  = bh >> 4;
    const int h  = bh & 15;
    const int i0 = blockIdx.x * 128;

    const int tid = threadIdx.x;

    if (tid < 128) {
        float z = 0.f;
#pragma unroll
        for (int jt = 0; jt < JT; jt++)
            z += zpart[((size_t)bh * JT + jt) * SEQ + i0 + tid];
        invZ[tid] = 1.f / z;
    }
    __syncthreads();

    float* Pb = attn + ((size_t)bh * SEQ + i0) * SEQ;
    const float* Vb = v + (size_t)bh * SEQ * HD;

    const int rb = tid >> 4;           // 0..15
    const int c4 = (tid & 15) * 4;     // 0..60
    const int ty = tid >> 4;
    const int tx = tid & 15;

    float acc[8][4];
#pragma unroll
    for (int i = 0; i < 8; i++)
#pragma unroll
        for (int j = 0; j < 4; j++) acc[i][j] = 0.f;

    for (int k0 = 0; k0 < SEQ; k0 += 64) {
        // P tile 128x64: normalize, write back, stage transposed
#pragma unroll
        for (int t = 0; t < 8; t++) {
            int r = rb + t * 16;
            float iz = invZ[r];
            float4 e = *(const float4*)&Pb[(size_t)r * SEQ + k0 + c4];
            float4 p = {e.x * iz, e.y * iz, e.z * iz, e.w * iz};
            *(float4*)&Pb[(size_t)r * SEQ + k0 + c4] = p;
            Pt[c4 + 0][r] = p.x; Pt[c4 + 1][r] = p.y;
            Pt[c4 + 2][r] = p.z; Pt[c4 + 3][r] = p.w;
        }
        // V tile 64x64
#pragma unroll
        for (int t = 0; t < 4; t++) {
            int r = rb + t * 16;
            float4 vv = *(const float4*)&Vb[(size_t)(k0 + r) * HD + c4];
            *(float4*)&Vs[r][c4] = vv;
        }
        __syncthreads();

#pragma unroll
        for (int kk = 0; kk < 64; kk++) {
            float4 a0 = *(const float4*)&Pt[kk][ty * 8];
            float4 a1 = *(const float4*)&Pt[kk][ty * 8 + 4];
            float4 bb = *(const float4*)&Vs[kk][tx * 4];
            float av[8] = {a0.x, a0.y, a0.z, a0.w, a1.x, a1.y, a1.z, a1.w};
            float bv[4] = {bb.x, bb.y, bb.z, bb.w};
#pragma unroll
            for (int i = 0; i < 8; i++)
#pragma unroll
                for (int j = 0; j < 4; j++)
                    acc[i][j] = fmaf(av[i], bv[j], acc[i][j]);
        }
        __syncthreads();
    }

#pragma unroll
    for (int i = 0; i < 8; i++) {
        float4 o = {acc[i][0], acc[i][1], acc[i][2], acc[i][3]};
        *(float4*)&ctx[((size_t)b * SEQ + i0 + ty * 8 + i) * DM + h * HD + tx * 4] = o;
    }
}

// ---------------------------------------------------------------------------
// Launch
// ---------------------------------------------------------------------------
extern "C" void kernel_launch(void* const* d_in, const int* in_sizes, int n_in,
                              void* d_out, int out_size)
{
    const float* query = (const float*)d_in[0];
    const float* key   = (const float*)d_in[1];
    const float* value = (const float*)d_in[2];
    const float* Wq    = (const float*)d_in[3];
    const float* bq    = (const float*)d_in[4];
    const float* Wk    = (const float*)d_in[5];
    const float* bk    = (const float*)d_in[6];
    const float* Wv    = (const float*)d_in[7];
    const float* bv    = (const float*)d_in[8];
    const float* Wo    = (const float*)d_in[9];
    const float* bo    = (const float*)d_in[10];
    const float* reso  = (const float*)d_in[11];
    const float* phas  = (const float*)d_in[12];

    float *qg, *kg, *vg, *ctx, *zp, *scratch;
    cudaGetSymbolAddress((void**)&qg,      g_q);
    cudaGetSymbolAddress((void**)&kg,      g_k);
    cudaGetSymbolAddress((void**)&vg,      g_v);
    cudaGetSymbolAddress((void**)&ctx,     g_ctx);
    cudaGetSymbolAddress((void**)&zp,      g_zpart);
    cudaGetSymbolAddress((void**)&scratch, g_attn_scratch);

    float* out_ptr = (float*)d_out;
    const bool attn_in_out = ((size_t)out_size >= OUT_ELEMS + ATTN_ELEMS);
    float* attn_ptr = attn_in_out ? (out_ptr + OUT_ELEMS) : scratch;

    // 1) QKV projections, fused into one launch (grid.z selects q/k/v)
    dim3 gP(DM / 128, MTOT / 128, 3);   // (8, 32, 3) = 768 CTAs
    sgemm_tn<0><<<gP, 256>>>(query, key, value, Wq, Wk, Wv, bq, bk, bv,
                             qg, kg, vg, MTOT, DM, DM);

    // 2) Scores + modulation + exp (unnormalized) + partial row sums
    dim3 gS(SEQ / 128, SEQ / 128, BATCH * NH);   // (16, 16, 32) = 8192 CTAs
    scores_kernel<<<gS, 256>>>(qg, kg, reso, phas, attn_ptr, zp);

    // 3) Fused normalize + attn write-back + PV
    dim3 gV(SEQ / 128, BATCH * NH);              // (16, 32) = 512 CTAs
    pv_fused_kernel<<<gV, 256>>>(attn_ptr, vg, zp, ctx);

    // 4) Output projection -> d_out
    dim3 gO(DM / 128, MTOT / 128, 1);
    sgemm_tn<1><<<gO, 256>>>(ctx, nullptr, nullptr, Wo, nullptr, nullptr,
                             bo, nullptr, nullptr, out_ptr, nullptr, nullptr,
                             MTOT, DM, DM);
}

// round 4
// speedup vs baseline: 1.2822x; 1.1975x over previous
#include <cuda_runtime.h>
#include <cuda_bf16.h>
#include <mma.h>
#include <math.h>
#include <stdint.h>

using namespace nvcuda;

// Problem constants
#define BATCH 2
#define SEQ   2048
#define DM    1024
#define NH    16
#define HD    64
#define MTOT  (BATCH*SEQ)   // 4096
#define JT    (SEQ/128)     // 16 j-tiles per row

static const size_t OUT_ELEMS  = (size_t)BATCH * SEQ * DM;
static const size_t ATTN_ELEMS = (size_t)BATCH * NH * SEQ * SEQ;

// Device scratch
__device__ float g_q  [BATCH*NH*SEQ*HD];
__device__ float g_k  [BATCH*NH*SEQ*HD];
__device__ float g_v  [BATCH*NH*SEQ*HD];
__device__ float g_ctx[BATCH*SEQ*DM];
__device__ float g_zpart[(size_t)BATCH*NH*JT*SEQ];
__device__ float g_attn_scratch[(size_t)BATCH*NH*SEQ*SEQ];

// ---------------------------------------------------------------------------
// HMMA (wmma) GEMM, bf16x3 split precision, fp32 accumulate.
// C[m,n] = sum_k A[m,k]*W[n,k] + bias[n]
// CTA: 128x128 tile, 8 warps (4 row-groups x 2 col-groups), warp = 32x64.
// K-chunks of 32 staged in smem as bf16 hi/lo.
// MODE 0: fused QKV via blockIdx.z, head-layout output. MODE 1: row-major.
// ---------------------------------------------------------------------------
#define KC  32
#define LDA 40   // bf16 row stride in smem (32 + 8 pad)

template<int MODE>
__global__ void __launch_bounds__(256)
gemm_wmma(const float* __restrict__ A0, const float* __restrict__ A1, const float* __restrict__ A2,
          const float* __restrict__ W0, const float* __restrict__ W1, const float* __restrict__ W2,
          const float* __restrict__ bb0, const float* __restrict__ bb1, const float* __restrict__ bb2,
          float* __restrict__ C0, float* __restrict__ C1, float* __restrict__ C2,
          int M, int N, int K)
{
    const float* A; const float* W; const float* bias; float* C;
    if (MODE == 0) {
        int z = blockIdx.z;
        A    = (z == 0) ? A0 : (z == 1) ? A1 : A2;
        W    = (z == 0) ? W0 : (z == 1) ? W1 : W2;
        bias = (z == 0) ? bb0 : (z == 1) ? bb1 : bb2;
        C    = (z == 0) ? C0 : (z == 1) ? C1 : C2;
    } else { A = A0; W = W0; bias = bb0; C = C0; }

    __shared__ __align__(16) __nv_bfloat16 sAhi[128 * LDA];
    __shared__ __align__(16) __nv_bfloat16 sAlo[128 * LDA];
    __shared__ __align__(16) __nv_bfloat16 sBhi[128 * LDA];
    __shared__ __align__(16) __nv_bfloat16 sBlo[128 * LDA];

    const int tid = threadIdx.x;
    const int wid = tid >> 5;
    const int lane = tid & 31;
    const int wr = wid & 3;     // warp row group: 32 rows each
    const int wc = wid >> 2;    // warp col group: 64 cols each
    const int m0 = blockIdx.y * 128;
    const int n0 = blockIdx.x * 128;

    wmma::fragment<wmma::accumulator, 16, 16, 16, float> acc[2][4];
#pragma unroll
    for (int i = 0; i < 2; i++)
#pragma unroll
        for (int j = 0; j < 4; j++) wmma::fill_fragment(acc[i][j], 0.f);

    const int row_l = tid >> 3;        // 0..31  (load helper: 4 rows per pass)
    const int c4    = (tid & 7) * 4;   // 0..28

    for (int k0 = 0; k0 < K; k0 += KC) {
        // Stage A and W chunk (128x32 fp32 each) as bf16 hi/lo
#pragma unroll
        for (int t = 0; t < 4; t++) {
            int row = row_l + t * 32;
            float4 a = *(const float4*)&A[(size_t)(m0 + row) * K + k0 + c4];
            float4 w = *(const float4*)&W[(size_t)(n0 + row) * K + k0 + c4];

            __nv_bfloat16 ahx = __float2bfloat16(a.x), ahy = __float2bfloat16(a.y);
            __nv_bfloat16 ahz = __float2bfloat16(a.z), ahw = __float2bfloat16(a.w);
            __nv_bfloat162 ah0 = {ahx, ahy}, ah1 = {ahz, ahw};
            __nv_bfloat162 al0 = {__float2bfloat16(a.x - __bfloat162float(ahx)),
                                  __float2bfloat16(a.y - __bfloat162float(ahy))};
            __nv_bfloat162 al1 = {__float2bfloat16(a.z - __bfloat162float(ahz)),
                                  __float2bfloat16(a.w - __bfloat162float(ahw))};
            *(uint2*)&sAhi[row * LDA + c4] = make_uint2(*(uint32_t*)&ah0, *(uint32_t*)&ah1);
            *(uint2*)&sAlo[row * LDA + c4] = make_uint2(*(uint32_t*)&al0, *(uint32_t*)&al1);

            __nv_bfloat16 whx = __float2bfloat16(w.x), why = __float2bfloat16(w.y);
            __nv_bfloat16 whz = __float2bfloat16(w.z), whw = __float2bfloat16(w.w);
            __nv_bfloat162 wh0 = {whx, why}, wh1 = {whz, whw};
            __nv_bfloat162 wl0 = {__float2bfloat16(w.x - __bfloat162float(whx)),
                                  __float2bfloat16(w.y - __bfloat162float(why))};
            __nv_bfloat162 wl1 = {__float2bfloat16(w.z - __bfloat162float(whz)),
                                  __float2bfloat16(w.w - __bfloat162float(whw))};
            *(uint2*)&sBhi[row * LDA + c4] = make_uint2(*(uint32_t*)&wh0, *(uint32_t*)&wh1);
            *(uint2*)&sBlo[row * LDA + c4] = make_uint2(*(uint32_t*)&wl0, *(uint32_t*)&wl1);
        }
        __syncthreads();

#pragma unroll
        for (int kk = 0; kk < KC; kk += 16) {
            wmma::fragment<wmma::matrix_a, 16, 16, 16, __nv_bfloat16, wmma::row_major> aHi[2], aLo[2];
            wmma::fragment<wmma::matrix_b, 16, 16, 16, __nv_bfloat16, wmma::col_major> bHi[4], bLo[4];
#pragma unroll
            for (int i = 0; i < 2; i++) {
                const __nv_bfloat16* pa = &sAhi[(wr * 32 + i * 16) * LDA + kk];
                const __nv_bfloat16* pl = &sAlo[(wr * 32 + i * 16) * LDA + kk];
                wmma::load_matrix_sync(aHi[i], pa, LDA);
                wmma::load_matrix_sync(aLo[i], pl, LDA);
            }
#pragma unroll
            for (int j = 0; j < 4; j++) {
                const __nv_bfloat16* pb = &sBhi[(wc * 64 + j * 16) * LDA + kk];
                const __nv_bfloat16* pl = &sBlo[(wc * 64 + j * 16) * LDA + kk];
                wmma::load_matrix_sync(bHi[j], pb, LDA);
                wmma::load_matrix_sync(bLo[j], pl, LDA);
            }
#pragma unroll
            for (int i = 0; i < 2; i++)
#pragma unroll
                for (int j = 0; j < 4; j++) {
                    wmma::mma_sync(acc[i][j], aHi[i], bHi[j], acc[i][j]);
                    wmma::mma_sync(acc[i][j], aHi[i], bLo[j], acc[i][j]);
                    wmma::mma_sync(acc[i][j], aLo[i], bHi[j], acc[i][j]);
                }
        }
        __syncthreads();
    }

    // Epilogue: per-warp 16x16 staging (reuse sAhi as fp32 scratch), bias, store.
    float* scratch = (float*)sAhi;           // 8 warps x 16x20 fp32 = 10240 B
    float* ws = scratch + wid * 16 * 20;
    const int er = lane >> 1;                // 0..15
    const int ec = (lane & 1) * 8;           // 0 or 8

#pragma unroll
    for (int i = 0; i < 2; i++)
#pragma unroll
        for (int j = 0; j < 4; j++) {
            wmma::store_matrix_sync(ws, acc[i][j], 20, wmma::mem_row_major);
            __syncwarp();
            int grow = m0 + wr * 32 + i * 16 + er;
            int col  = n0 + wc * 64 + j * 16 + ec;
            float4 b0 = *(const float4*)&bias[col];
            float4 b1 = *(const float4*)&bias[col + 4];
            float4 v0, v1;
            v0.x = ws[er * 20 + ec + 0] + b0.x;
            v0.y = ws[er * 20 + ec + 1] + b0.y;
            v0.z = ws[er * 20 + ec + 2] + b0.z;
            v0.w = ws[er * 20 + ec + 3] + b0.w;
            v1.x = ws[er * 20 + ec + 4] + b1.x;
            v1.y = ws[er * 20 + ec + 5] + b1.y;
            v1.z = ws[er * 20 + ec + 6] + b1.z;
            v1.w = ws[er * 20 + ec + 7] + b1.w;
            if (MODE == 0) {
                int b  = grow >> 11;
                int s  = grow & (SEQ - 1);
                int h  = col >> 6;
                int dd = col & (HD - 1);
                float* dst = &C[(((size_t)(b * NH + h)) * SEQ + s) * HD + dd];
                *(float4*)dst       = v0;
                *(float4*)(dst + 4) = v1;
            } else {
                float* dst = &C[(size_t)grow * N + col];
                *(float4*)dst       = v0;
                *(float4*)(dst + 4) = v1;
            }
            __syncwarp();
        }
}

// ---------------------------------------------------------------------------
// Scores: per (b,h), 128x128 tile of S = (q k^T)/8 ; s += res*sin(s+phase);
// writes UNNORMALIZED exp(s) + partial row sums.
// ---------------------------------------------------------------------------
__global__ void __launch_bounds__(256)
scores_kernel(const float* __restrict__ q, const float* __restrict__ k,
              const float* __restrict__ res, const float* __restrict__ ph,
              float* __restrict__ attn, float* __restrict__ zpart)
{
    __shared__ float qt[HD][132];
    __shared__ float kt[HD][132];

    const int bh = blockIdx.z;
    const int h  = bh & (NH - 1);
    const int i0 = blockIdx.y * 128;
    const int j0 = blockIdx.x * 128;

    const float* qb = q + (size_t)bh * SEQ * HD;
    const float* kb = k + (size_t)bh * SEQ * HD;

    const int tid = threadIdx.x;
    const int rb  = tid >> 4;
    const int c4  = (tid & 15) * 4;

#pragma unroll
    for (int t = 0; t < 8; t++) {
        int r = rb + t * 16;
        float4 a = *(const float4*)&qb[(size_t)(i0 + r) * HD + c4];
        qt[c4 + 0][r] = a.x; qt[c4 + 1][r] = a.y;
        qt[c4 + 2][r] = a.z; qt[c4 + 3][r] = a.w;
        float4 b = *(const float4*)&kb[(size_t)(j0 + r) * HD + c4];
        kt[c4 + 0][r] = b.x; kt[c4 + 1][r] = b.y;
        kt[c4 + 2][r] = b.z; kt[c4 + 3][r] = b.w;
    }
    __syncthreads();

    const int ty = tid >> 4;
    const int tx = tid & 15;

    float acc[8][8];
#pragma unroll
    for (int i = 0; i < 8; i++)
#pragma unroll
        for (int j = 0; j < 8; j++) acc[i][j] = 0.f;

#pragma unroll
    for (int d = 0; d < HD; d++) {
        float4 a0 = *(const float4*)&qt[d][ty * 8];
        float4 a1 = *(const float4*)&qt[d][ty * 8 + 4];
        float4 b0 = *(const float4*)&kt[d][tx * 8];
        float4 b1 = *(const float4*)&kt[d][tx * 8 + 4];
        float av[8] = {a0.x, a0.y, a0.z, a0.w, a1.x, a1.y, a1.z, a1.w};
        float bv[8] = {b0.x, b0.y, b0.z, b0.w, b1.x, b1.y, b1.z, b1.w};
#pragma unroll
        for (int i = 0; i < 8; i++)
#pragma unroll
            for (int j = 0; j < 8; j++)
                acc[i][j] = fmaf(av[i], bv[j], acc[i][j]);
    }

    const float R = res[h];
    const float P = ph[h];
    float rowsum[8];
#pragma unroll
    for (int i = 0; i < 8; i++) rowsum[i] = 0.f;

#pragma unroll
    for (int i = 0; i < 8; i++) {
        float4 o0, o1;
#pragma unroll
        for (int j = 0; j < 8; j++) {
            float s = acc[i][j] * 0.125f;
            s += R * __sinf(s + P);
            float e = __expf(s);
            rowsum[i] += e;
            if (j < 4) (&o0.x)[j] = e; else (&o1.x)[j - 4] = e;
        }
        float* orow = attn + ((size_t)bh * SEQ + i0 + ty * 8 + i) * SEQ + j0;
        *(float4*)&orow[tx * 8]     = o0;
        *(float4*)&orow[tx * 8 + 4] = o1;
    }

    __syncthreads();
    float* red = (float*)qt;
#pragma unroll
    for (int i = 0; i < 8; i++) red[(ty * 8 + i) * 16 + tx] = rowsum[i];
    __syncthreads();
    if (tid < 128) {
        float s = 0.f;
#pragma unroll
        for (int t = 0; t < 16; t++) s += red[tid * 16 + t];
        zpart[((size_t)bh * JT + blockIdx.x) * SEQ + i0 + tid] = s;
    }
}

// ---------------------------------------------------------------------------
// Fused normalize + PV
// ---------------------------------------------------------------------------
__global__ void __launch_bounds__(256)
pv_fused_kernel(float* __restrict__ attn, const float* __restrict__ v,
                const float* __restrict__ zpart, float* __restrict__ ctx)
{
    __shared__ float Pt[64][132];
    __shared__ float Vs[64][68];
    __shared__ float invZ[128];

    const int bh = blockIdx.y;
    const int b  = bh >> 4;
    const int h  = bh & 15;
    const int i0 = blockIdx.x * 128;

    const int tid = threadIdx.x;

    if (tid < 128) {
        float z = 0.f;
#pragma unroll
        for (int jt = 0; jt < JT; jt++)
            z += zpart[((size_t)bh * JT + jt) * SEQ + i0 + tid];
        invZ[tid] = 1.f / z;
    }
    __syncthreads();

    float* Pb = attn + ((size_t)bh * SEQ + i0) * SEQ;
    const float* Vb = v + (size_t)bh * SEQ * HD;

    const int rb = tid >> 4;
    const int c4 = (tid & 15) * 4;
    const int ty = tid >> 4;
    const int tx = tid & 15;

    float acc[8][4];
#pragma unroll
    for (int i = 0; i < 8; i++)
#pragma unroll
        for (int j = 0; j < 4; j++) acc[i][j] = 0.f;

    for (int k0 = 0; k0 < SEQ; k0 += 64) {
#pragma unroll
        for (int t = 0; t < 8; t++) {
            int r = rb + t * 16;
            float iz = invZ[r];
            float4 e = *(const float4*)&Pb[(size_t)r * SEQ + k0 + c4];
            float4 p = {e.x * iz, e.y * iz, e.z * iz, e.w * iz};
            *(float4*)&Pb[(size_t)r * SEQ + k0 + c4] = p;
            Pt[c4 + 0][r] = p.x; Pt[c4 + 1][r] = p.y;
            Pt[c4 + 2][r] = p.z; Pt[c4 + 3][r] = p.w;
        }
#pragma unroll
        for (int t = 0; t < 4; t++) {
            int r = rb + t * 16;
            float4 vv = *(const float4*)&Vb[(size_t)(k0 + r) * HD + c4];
            *(float4*)&Vs[r][c4] = vv;
        }
        __syncthreads();

#pragma unroll
        for (int kk = 0; kk < 64; kk++) {
            float4 a0 = *(const float4*)&Pt[kk][ty * 8];
            float4 a1 = *(const float4*)&Pt[kk][ty * 8 + 4];
            float4 bb = *(const float4*)&Vs[kk][tx * 4];
            float av[8] = {a0.x, a0.y, a0.z, a0.w, a1.x, a1.y, a1.z, a1.w};
            float bv[4] = {bb.x, bb.y, bb.z, bb.w};
#pragma unroll
            for (int i = 0; i < 8; i++)
#pragma unroll
                for (int j = 0; j < 4; j++)
                    acc[i][j] = fmaf(av[i], bv[j], acc[i][j]);
        }
        __syncthreads();
    }

#pragma unroll
    for (int i = 0; i < 8; i++) {
        float4 o = {acc[i][0], acc[i][1], acc[i][2], acc[i][3]};
        *(float4*)&ctx[((size_t)b * SEQ + i0 + ty * 8 + i) * DM + h * HD + tx * 4] = o;
    }
}

// ---------------------------------------------------------------------------
// Launch
// ---------------------------------------------------------------------------
extern "C" void kernel_launch(void* const* d_in, const int* in_sizes, int n_in,
                              void* d_out, int out_size)
{
    const float* query = (const float*)d_in[0];
    const float* key   = (const float*)d_in[1];
    const float* value = (const float*)d_in[2];
    const float* Wq    = (const float*)d_in[3];
    const float* bq    = (const float*)d_in[4];
    const float* Wk    = (const float*)d_in[5];
    const float* bk    = (const float*)d_in[6];
    const float* Wv    = (const float*)d_in[7];
    const float* bv    = (const float*)d_in[8];
    const float* Wo    = (const float*)d_in[9];
    const float* bo    = (const float*)d_in[10];
    const float* reso  = (const float*)d_in[11];
    const float* phas  = (const float*)d_in[12];

    float *qg, *kg, *vg, *ctx, *zp, *scratch;
    cudaGetSymbolAddress((void**)&qg,      g_q);
    cudaGetSymbolAddress((void**)&kg,      g_k);
    cudaGetSymbolAddress((void**)&vg,      g_v);
    cudaGetSymbolAddress((void**)&ctx,     g_ctx);
    cudaGetSymbolAddress((void**)&zp,      g_zpart);
    cudaGetSymbolAddress((void**)&scratch, g_attn_scratch);

    float* out_ptr = (float*)d_out;
    const bool attn_in_out = ((size_t)out_size >= OUT_ELEMS + ATTN_ELEMS);
    float* attn_ptr = attn_in_out ? (out_ptr + OUT_ELEMS) : scratch;

    // 1) QKV projections on HMMA bf16x3, fused launch
    dim3 gP(DM / 128, MTOT / 128, 3);   // (8, 32, 3)
    gemm_wmma<0><<<gP, 256>>>(query, key, value, Wq, Wk, Wv, bq, bk, bv,
                              qg, kg, vg, MTOT, DM, DM);

    // 2) Scores + modulation + exp (unnormalized) + partial row sums
    dim3 gS(SEQ / 128, SEQ / 128, BATCH * NH);
    scores_kernel<<<gS, 256>>>(qg, kg, reso, phas, attn_ptr, zp);

    // 3) Fused normalize + attn write-back + PV
    dim3 gV(SEQ / 128, BATCH * NH);
    pv_fused_kernel<<<gV, 256>>>(attn_ptr, vg, zp, ctx);

    // 4) Output projection on HMMA bf16x3
    dim3 gO(DM / 128, MTOT / 128, 1);
    gemm_wmma<1><<<gO, 256>>>(ctx, nullptr, nullptr, Wo, nullptr, nullptr,
                              bo, nullptr, nullptr, out_ptr, nullptr, nullptr,
                              MTOT, DM, DM);
}

// round 5
// speedup vs baseline: 1.6860x; 1.3149x over previous
#include <cuda_runtime.h>
#include <cuda_bf16.h>
#include <mma.h>
#include <math.h>
#include <stdint.h>

using namespace nvcuda;

// Problem constants
#define BATCH 2
#define SEQ   2048
#define DM    1024
#define NH    16
#define HD    64
#define MTOT  (BATCH*SEQ)   // 4096
#define JT    (SEQ/128)     // 16 j-tiles
#define KC    64            // gemm k-chunk
#define LDK   72            // smem bf16 row stride (64 + 8 pad)
#define STG_LD 136          // scores fp32 staging stride

static const size_t OUT_ELEMS  = (size_t)BATCH * SEQ * DM;
static const size_t ATTN_ELEMS = (size_t)BATCH * NH * SEQ * SEQ;

// ---------------------------------------------------------------------------
// Device scratch
// ---------------------------------------------------------------------------
__device__ __nv_bfloat16 g_xq_hi[MTOT*DM], g_xq_lo[MTOT*DM];
__device__ __nv_bfloat16 g_xk_hi[MTOT*DM], g_xk_lo[MTOT*DM];
__device__ __nv_bfloat16 g_xv_hi[MTOT*DM], g_xv_lo[MTOT*DM];
__device__ __nv_bfloat16 g_wq_hi[DM*DM], g_wq_lo[DM*DM];
__device__ __nv_bfloat16 g_wk_hi[DM*DM], g_wk_lo[DM*DM];
__device__ __nv_bfloat16 g_wv_hi[DM*DM], g_wv_lo[DM*DM];
__device__ __nv_bfloat16 g_wo_hi[DM*DM], g_wo_lo[DM*DM];
__device__ __nv_bfloat16 g_q_hi[BATCH*NH*SEQ*HD], g_q_lo[BATCH*NH*SEQ*HD];
__device__ __nv_bfloat16 g_k_hi[BATCH*NH*SEQ*HD], g_k_lo[BATCH*NH*SEQ*HD];
__device__ float         g_v   [BATCH*NH*SEQ*HD];
__device__ __nv_bfloat16 g_ctx_hi[MTOT*DM], g_ctx_lo[MTOT*DM];
__device__ float g_zpart[(size_t)BATCH*NH*JT*SEQ];
__device__ float g_attn_scratch[(size_t)BATCH*NH*SEQ*SEQ];

// ---------------------------------------------------------------------------
// Helpers
// ---------------------------------------------------------------------------
__device__ __forceinline__ void cp16(void* dst, const void* src) {
    asm volatile("cp.async.cg.shared.global [%0], [%1], 16;"
                 :: "r"((uint32_t)__cvta_generic_to_shared(dst)), "l"(src));
}
__device__ __forceinline__ void cp_commit() {
    asm volatile("cp.async.commit_group;");
}
__device__ __forceinline__ uint32_t bfpack(float a, float b) {
    __nv_bfloat162 t(__float2bfloat16(a), __float2bfloat16(b));
    return *(uint32_t*)&t;
}

// fp32 -> bf16 hi/lo split (streaming)
__global__ void __launch_bounds__(256)
convert_split(const float4* __restrict__ src, uint2* __restrict__ hi,
              uint2* __restrict__ lo, int n4)
{
    int i = blockIdx.x * 256 + threadIdx.x;
    if (i >= n4) return;
    float4 v = src[i];
    __nv_bfloat16 hx = __float2bfloat16(v.x), hy = __float2bfloat16(v.y);
    __nv_bfloat16 hz = __float2bfloat16(v.z), hw = __float2bfloat16(v.w);
    __nv_bfloat162 h01(hx, hy), h23(hz, hw);
    hi[i] = make_uint2(*(uint32_t*)&h01, *(uint32_t*)&h23);
    lo[i] = make_uint2(bfpack(v.x - __bfloat162float(hx), v.y - __bfloat162float(hy)),
                       bfpack(v.z - __bfloat162float(hz), v.w - __bfloat162float(hw)));
}

// ---------------------------------------------------------------------------
// HMMA GEMM, pre-split bf16 hi/lo inputs, cp.async double-buffered.
// C[m,n] = sum_k A[m,k]*W[n,k] + bias[n]
// CTA 128x128, 8 warps (4x2), warp 32x64. KC=64 chunks.
// MODE 0: QKV fused via blockIdx.z; z=0/1 -> bf16 hi/lo head-layout out,
//         z=2 -> fp32 head-layout out. MODE 1: fp32 row-major out.
// ---------------------------------------------------------------------------
struct GemmPtrs {
    const __nv_bfloat16 *Ahi[3], *Alo[3], *Whi[3], *Wlo[3];
    const float* bias[3];
    float* outF[3];
    __nv_bfloat16 *outHi[3], *outLo[3];
};

#define GTILE (128*LDK)      // elements per smem matrix
#define GSTAGE (4*GTILE)     // elements per stage

template<int MODE>
__global__ void __launch_bounds__(256)
gemm_bf16(GemmPtrs P, int M, int N, int K)
{
    extern __shared__ __align__(16) __nv_bfloat16 sm[];
    const int z = (MODE == 0) ? blockIdx.z : 0;
    const __nv_bfloat16* Ahi = P.Ahi[z];
    const __nv_bfloat16* Alo = P.Alo[z];
    const __nv_bfloat16* Whi = P.Whi[z];
    const __nv_bfloat16* Wlo = P.Wlo[z];
    const float* bias = P.bias[z];

    const int tid = threadIdx.x;
    const int wid = tid >> 5;
    const int lane = tid & 31;
    const int wr = wid & 3;
    const int wc = wid >> 2;
    const int m0 = blockIdx.y * 128;
    const int n0 = blockIdx.x * 128;

    wmma::fragment<wmma::accumulator, 16, 16, 16, float> acc[2][4];
#pragma unroll
    for (int i = 0; i < 2; i++)
#pragma unroll
        for (int j = 0; j < 4; j++) wmma::fill_fragment(acc[i][j], 0.f);

    const int NC = K / KC;   // 16

    auto stage_copy = [&](int c, int s) {
        const int k0 = c * KC;
        __nv_bfloat16* base = sm + s * GSTAGE;
#pragma unroll
        for (int t = 0; t < 4; t++) {
            int chunk = tid + t * 256;            // 0..1023
            int row  = chunk >> 3;                // 0..127
            int coff = (chunk & 7) * 8;           // 0..56
            cp16(base + 0*GTILE + row * LDK + coff, Ahi + (size_t)(m0 + row) * K + k0 + coff);
            cp16(base + 1*GTILE + row * LDK + coff, Alo + (size_t)(m0 + row) * K + k0 + coff);
            cp16(base + 2*GTILE + row * LDK + coff, Whi + (size_t)(n0 + row) * K + k0 + coff);
            cp16(base + 3*GTILE + row * LDK + coff, Wlo + (size_t)(n0 + row) * K + k0 + coff);
        }
        cp_commit();
    };

    stage_copy(0, 0);

    for (int c = 0; c < NC; c++) {
        if (c + 1 < NC) stage_copy(c + 1, (c + 1) & 1);
        if (c + 1 < NC) asm volatile("cp.async.wait_group 1;");
        else            asm volatile("cp.async.wait_group 0;");
        __syncthreads();

        const __nv_bfloat16* base = sm + (c & 1) * GSTAGE;
        const __nv_bfloat16* sAhi = base + 0*GTILE;
        const __nv_bfloat16* sAlo = base + 1*GTILE;
        const __nv_bfloat16* sWhi = base + 2*GTILE;
        const __nv_bfloat16* sWlo = base + 3*GTILE;

#pragma unroll
        for (int kk = 0; kk < KC; kk += 16) {
            wmma::fragment<wmma::matrix_a, 16, 16, 16, __nv_bfloat16, wmma::row_major> aHi[2], aLo[2];
            wmma::fragment<wmma::matrix_b, 16, 16, 16, __nv_bfloat16, wmma::col_major> bHi[4], bLo[4];
#pragma unroll
            for (int i = 0; i < 2; i++) {
                wmma::load_matrix_sync(aHi[i], &sAhi[(wr * 32 + i * 16) * LDK + kk], LDK);
                wmma::load_matrix_sync(aLo[i], &sAlo[(wr * 32 + i * 16) * LDK + kk], LDK);
            }
#pragma unroll
            for (int j = 0; j < 4; j++) {
                wmma::load_matrix_sync(bHi[j], &sWhi[(wc * 64 + j * 16) * LDK + kk], LDK);
                wmma::load_matrix_sync(bLo[j], &sWlo[(wc * 64 + j * 16) * LDK + kk], LDK);
            }
#pragma unroll
            for (int i = 0; i < 2; i++)
#pragma unroll
                for (int j = 0; j < 4; j++) {
                    wmma::mma_sync(acc[i][j], aHi[i], bHi[j], acc[i][j]);
                    wmma::mma_sync(acc[i][j], aHi[i], bLo[j], acc[i][j]);
                    wmma::mma_sync(acc[i][j], aLo[i], bHi[j], acc[i][j]);
                }
        }
        __syncthreads();
    }

    // Epilogue
    float* scratch = (float*)sm;
    float* ws = scratch + wid * 16 * 20;
    const int er = lane >> 1;
    const int ec = (lane & 1) * 8;

#pragma unroll
    for (int i = 0; i < 2; i++)
#pragma unroll
        for (int j = 0; j < 4; j++) {
            wmma::store_matrix_sync(ws, acc[i][j], 20, wmma::mem_row_major);
            __syncwarp();
            int grow = m0 + wr * 32 + i * 16 + er;
            int col  = n0 + wc * 64 + j * 16 + ec;
            float4 b0 = *(const float4*)&bias[col];
            float4 b1 = *(const float4*)&bias[col + 4];
            float vv[8];
#pragma unroll
            for (int e = 0; e < 4; e++) vv[e]     = ws[er * 20 + ec + e]     + (&b0.x)[e];
#pragma unroll
            for (int e = 0; e < 4; e++) vv[e + 4] = ws[er * 20 + ec + 4 + e] + (&b1.x)[e];

            if (MODE == 0) {
                int b  = grow >> 11;
                int s  = grow & (SEQ - 1);
                int hh = col >> 6;
                int dd = col & (HD - 1);
                size_t off = (((size_t)(b * NH + hh)) * SEQ + s) * HD + dd;
                if (P.outHi[z]) {
                    uint4 uh, ul;
                    __nv_bfloat16 h[8];
#pragma unroll
                    for (int e = 0; e < 8; e++) h[e] = __float2bfloat16(vv[e]);
                    __nv_bfloat162 p0(h[0],h[1]), p1(h[2],h[3]), p2(h[4],h[5]), p3(h[6],h[7]);
                    uh = make_uint4(*(uint32_t*)&p0, *(uint32_t*)&p1, *(uint32_t*)&p2, *(uint32_t*)&p3);
                    ul.x = bfpack(vv[0]-__bfloat162float(h[0]), vv[1]-__bfloat162float(h[1]));
                    ul.y = bfpack(vv[2]-__bfloat162float(h[2]), vv[3]-__bfloat162float(h[3]));
                    ul.z = bfpack(vv[4]-__bfloat162float(h[4]), vv[5]-__bfloat162float(h[5]));
                    ul.w = bfpack(vv[6]-__bfloat162float(h[6]), vv[7]-__bfloat162float(h[7]));
                    *(uint4*)&P.outHi[z][off] = uh;
                    *(uint4*)&P.outLo[z][off] = ul;
                } else {
                    float* dst = &P.outF[z][off];
                    *(float4*)dst       = make_float4(vv[0], vv[1], vv[2], vv[3]);
                    *(float4*)(dst + 4) = make_float4(vv[4], vv[5], vv[6], vv[7]);
                }
            } else {
                float* dst = &P.outF[0][(size_t)grow * N + col];
                *(float4*)dst       = make_float4(vv[0], vv[1], vv[2], vv[3]);
                *(float4*)(dst + 4) = make_float4(vv[4], vv[5], vv[6], vv[7]);
            }
            __syncwarp();
        }
}

// ---------------------------------------------------------------------------
// Scores on HMMA: per (b,h), 128x128 tile of S = (q k^T)/8,
// s += res*sin(s+phase), e = exp(s) (unnormalized), partial row sums.
// Q/K are bf16 hi/lo, 3-term split product. Elementwise applied on fragments.
// ---------------------------------------------------------------------------
__global__ void __launch_bounds__(256)
scores_wmma(const __nv_bfloat16* __restrict__ qhi, const __nv_bfloat16* __restrict__ qlo,
            const __nv_bfloat16* __restrict__ khi, const __nv_bfloat16* __restrict__ klo,
            const float* __restrict__ res, const float* __restrict__ ph,
            float* __restrict__ attn, float* __restrict__ zpart)
{
    extern __shared__ __align__(16) __nv_bfloat16 sm2[];
    __nv_bfloat16* sQhi = sm2 + 0*GTILE;
    __nv_bfloat16* sQlo = sm2 + 1*GTILE;
    __nv_bfloat16* sKhi = sm2 + 2*GTILE;
    __nv_bfloat16* sKlo = sm2 + 3*GTILE;
    float* stage = (float*)sm2;

    const int bh = blockIdx.z;
    const int h  = bh & (NH - 1);
    const int i0 = blockIdx.y * 128;
    const int j0 = blockIdx.x * 128;
    const int tid = threadIdx.x;
    const int wid = tid >> 5;
    const int wr = wid & 3;
    const int wc = wid >> 2;

    const size_t qbase = (size_t)bh * SEQ * HD;

#pragma unroll
    for (int t = 0; t < 4; t++) {
        int chunk = tid + t * 256;
        int row  = chunk >> 3;
        int coff = (chunk & 7) * 8;
        cp16(sQhi + row * LDK + coff, qhi + qbase + (size_t)(i0 + row) * HD + coff);
        cp16(sQlo + row * LDK + coff, qlo + qbase + (size_t)(i0 + row) * HD + coff);
        cp16(sKhi + row * LDK + coff, khi + qbase + (size_t)(j0 + row) * HD + coff);
        cp16(sKlo + row * LDK + coff, klo + qbase + (size_t)(j0 + row) * HD + coff);
    }
    cp_commit();
    asm volatile("cp.async.wait_group 0;");
    __syncthreads();

    wmma::fragment<wmma::accumulator, 16, 16, 16, float> acc[2][4];
#pragma unroll
    for (int i = 0; i < 2; i++)
#pragma unroll
        for (int j = 0; j < 4; j++) wmma::fill_fragment(acc[i][j], 0.f);

#pragma unroll
    for (int kk = 0; kk < 64; kk += 16) {
        wmma::fragment<wmma::matrix_a, 16, 16, 16, __nv_bfloat16, wmma::row_major> aHi[2], aLo[2];
        wmma::fragment<wmma::matrix_b, 16, 16, 16, __nv_bfloat16, wmma::col_major> bHi[4], bLo[4];
#pragma unroll
        for (int i = 0; i < 2; i++) {
            wmma::load_matrix_sync(aHi[i], &sQhi[(wr * 32 + i * 16) * LDK + kk], LDK);
            wmma::load_matrix_sync(aLo[i], &sQlo[(wr * 32 + i * 16) * LDK + kk], LDK);
        }
#pragma unroll
        for (int j = 0; j < 4; j++) {
            wmma::load_matrix_sync(bHi[j], &sKhi[(wc * 64 + j * 16) * LDK + kk], LDK);
            wmma::load_matrix_sync(bLo[j], &sKlo[(wc * 64 + j * 16) * LDK + kk], LDK);
        }
#pragma unroll
        for (int i = 0; i < 2; i++)
#pragma unroll
            for (int j = 0; j < 4; j++) {
                wmma::mma_sync(acc[i][j], aHi[i], bHi[j], acc[i][j]);
                wmma::mma_sync(acc[i][j], aHi[i], bLo[j], acc[i][j]);
                wmma::mma_sync(acc[i][j], aLo[i], bHi[j], acc[i][j]);
            }
    }

    // harmonic modulation + exp, layout-independent per-element
    const float R = res[h];
    const float Pp = ph[h];
#pragma unroll
    for (int i = 0; i < 2; i++)
#pragma unroll
        for (int j = 0; j < 4; j++)
#pragma unroll
            for (int e = 0; e < acc[i][j].num_elements; e++) {
                float s = acc[i][j].x[e] * 0.125f;
                s += R * __sinf(s + Pp);
                acc[i][j].x[e] = __expf(s);
            }

    __syncthreads();   // done reading q/k smem; reuse as fp32 staging
#pragma unroll
    for (int i = 0; i < 2; i++)
#pragma unroll
        for (int j = 0; j < 4; j++)
            wmma::store_matrix_sync(&stage[(size_t)(wr * 32 + i * 16) * STG_LD + wc * 64 + j * 16],
                                    acc[i][j], STG_LD, wmma::mem_row_major);
    __syncthreads();

    // partial row sums (one half-row per thread, pair-combined)
    {
        int row  = tid >> 1;
        int base = (tid & 1) * 64;
        float s = 0.f;
        const float* pr = &stage[(size_t)row * STG_LD + base];
#pragma unroll
        for (int e = 0; e < 64; e += 4) {
            float4 v4 = *(const float4*)&pr[e];
            s += v4.x + v4.y + v4.z + v4.w;
        }
        s += __shfl_xor_sync(0xffffffffu, s, 1);
        if ((tid & 1) == 0)
            zpart[((size_t)bh * JT + blockIdx.x) * SEQ + i0 + row] = s;
    }

    // write attn tile (unnormalized exp)
#pragma unroll
    for (int t = 0; t < 16; t++) {
        int idx = tid + t * 256;          // 0..4095 float4 slots
        int row = idx >> 5;
        int c4  = (idx & 31) * 4;
        float4 v4 = *(const float4*)&stage[(size_t)row * STG_LD + c4];
        *(float4*)&attn[((size_t)bh * SEQ + i0 + row) * SEQ + j0 + c4] = v4;
    }
}

// ---------------------------------------------------------------------------
// Fused normalize + PV. attn normalized in place; ctx emitted as bf16 hi/lo.
// ---------------------------------------------------------------------------
__global__ void __launch_bounds__(256)
pv_fused_kernel(float* __restrict__ attn, const float* __restrict__ v,
                const float* __restrict__ zpart,
                __nv_bfloat16* __restrict__ ctxhi, __nv_bfloat16* __restrict__ ctxlo)
{
    __shared__ float Pt[64][132];
    __shared__ float Vs[64][68];
    __shared__ float invZ[128];

    const int bh = blockIdx.y;
    const int b  = bh >> 4;
    const int h  = bh & 15;
    const int i0 = blockIdx.x * 128;
    const int tid = threadIdx.x;

    if (tid < 128) {
        float z = 0.f;
#pragma unroll
        for (int jt = 0; jt < JT; jt++)
            z += zpart[((size_t)bh * JT + jt) * SEQ + i0 + tid];
        invZ[tid] = 1.f / z;
    }
    __syncthreads();

    float* Pb = attn + ((size_t)bh * SEQ + i0) * SEQ;
    const float* Vb = v + (size_t)bh * SEQ * HD;

    const int rb = tid >> 4;
    const int c4 = (tid & 15) * 4;
    const int ty = tid >> 4;
    const int tx = tid & 15;

    float acc[8][4];
#pragma unroll
    for (int i = 0; i < 8; i++)
#pragma unroll
        for (int j = 0; j < 4; j++) acc[i][j] = 0.f;

    for (int k0 = 0; k0 < SEQ; k0 += 64) {
#pragma unroll
        for (int t = 0; t < 8; t++) {
            int r = rb + t * 16;
            float iz = invZ[r];
            float4 e = *(const float4*)&Pb[(size_t)r * SEQ + k0 + c4];
            float4 p = {e.x * iz, e.y * iz, e.z * iz, e.w * iz};
            *(float4*)&Pb[(size_t)r * SEQ + k0 + c4] = p;
            Pt[c4 + 0][r] = p.x; Pt[c4 + 1][r] = p.y;
            Pt[c4 + 2][r] = p.z; Pt[c4 + 3][r] = p.w;
        }
#pragma unroll
        for (int t = 0; t < 4; t++) {
            int r = rb + t * 16;
            float4 vv = *(const float4*)&Vb[(size_t)(k0 + r) * HD + c4];
            *(float4*)&Vs[r][c4] = vv;
        }
        __syncthreads();

#pragma unroll
        for (int kk = 0; kk < 64; kk++) {
            float4 a0 = *(const float4*)&Pt[kk][ty * 8];
            float4 a1 = *(const float4*)&Pt[kk][ty * 8 + 4];
            float4 bb = *(const float4*)&Vs[kk][tx * 4];
            float av[8] = {a0.x, a0.y, a0.z, a0.w, a1.x, a1.y, a1.z, a1.w};
            float bv[4] = {bb.x, bb.y, bb.z, bb.w};
#pragma unroll
            for (int i = 0; i < 8; i++)
#pragma unroll
                for (int j = 0; j < 4; j++)
                    acc[i][j] = fmaf(av[i], bv[j], acc[i][j]);
        }
        __syncthreads();
    }

#pragma unroll
    for (int i = 0; i < 8; i++) {
        size_t off = ((size_t)b * SEQ + i0 + ty * 8 + i) * DM + h * HD + tx * 4;
        __nv_bfloat16 h0 = __float2bfloat16(acc[i][0]);
        __nv_bfloat16 h1 = __float2bfloat16(acc[i][1]);
        __nv_bfloat16 h2 = __float2bfloat16(acc[i][2]);
        __nv_bfloat16 h3 = __float2bfloat16(acc[i][3]);
        __nv_bfloat162 p0(h0, h1), p1(h2, h3);
        *(uint2*)&ctxhi[off] = make_uint2(*(uint32_t*)&p0, *(uint32_t*)&p1);
        uint2 ul;
        ul.x = bfpack(acc[i][0] - __bfloat162float(h0), acc[i][1] - __bfloat162float(h1));
        ul.y = bfpack(acc[i][2] - __bfloat162float(h2), acc[i][3] - __bfloat162float(h3));
        *(uint2*)&ctxlo[off] = ul;
    }
}

// ---------------------------------------------------------------------------
// Launch
// ---------------------------------------------------------------------------
extern "C" void kernel_launch(void* const* d_in, const int* in_sizes, int n_in,
                              void* d_out, int out_size)
{
    const float* query = (const float*)d_in[0];
    const float* key   = (const float*)d_in[1];
    const float* value = (const float*)d_in[2];
    const float* Wq    = (const float*)d_in[3];
    const float* bq    = (const float*)d_in[4];
    const float* Wk    = (const float*)d_in[5];
    const float* bk    = (const float*)d_in[6];
    const float* Wv    = (const float*)d_in[7];
    const float* bv    = (const float*)d_in[8];
    const float* Wo    = (const float*)d_in[9];
    const float* bo    = (const float*)d_in[10];
    const float* reso  = (const float*)d_in[11];
    const float* phas  = (const float*)d_in[12];

    __nv_bfloat16 *xqh,*xql,*xkh,*xkl,*xvh,*xvl, *wqh,*wql,*wkh,*wkl,*wvh,*wvl,*woh,*wol;
    __nv_bfloat16 *qh,*ql,*kh,*kl, *cxh,*cxl;
    float *vg, *zp, *scratch;
    cudaGetSymbolAddress((void**)&xqh, g_xq_hi); cudaGetSymbolAddress((void**)&xql, g_xq_lo);
    cudaGetSymbolAddress((void**)&xkh, g_xk_hi); cudaGetSymbolAddress((void**)&xkl, g_xk_lo);
    cudaGetSymbolAddress((void**)&xvh, g_xv_hi); cudaGetSymbolAddress((void**)&xvl, g_xv_lo);
    cudaGetSymbolAddress((void**)&wqh, g_wq_hi); cudaGetSymbolAddress((void**)&wql, g_wq_lo);
    cudaGetSymbolAddress((void**)&wkh, g_wk_hi); cudaGetSymbolAddress((void**)&wkl, g_wk_lo);
    cudaGetSymbolAddress((void**)&wvh, g_wv_hi); cudaGetSymbolAddress((void**)&wvl, g_wv_lo);
    cudaGetSymbolAddress((void**)&woh, g_wo_hi); cudaGetSymbolAddress((void**)&wol, g_wo_lo);
    cudaGetSymbolAddress((void**)&qh,  g_q_hi);  cudaGetSymbolAddress((void**)&ql,  g_q_lo);
    cudaGetSymbolAddress((void**)&kh,  g_k_hi);  cudaGetSymbolAddress((void**)&kl,  g_k_lo);
    cudaGetSymbolAddress((void**)&vg,  g_v);
    cudaGetSymbolAddress((void**)&cxh, g_ctx_hi); cudaGetSymbolAddress((void**)&cxl, g_ctx_lo);
    cudaGetSymbolAddress((void**)&zp,  g_zpart);
    cudaGetSymbolAddress((void**)&scratch, g_attn_scratch);

    float* out_ptr = (float*)d_out;
    const bool attn_in_out = ((size_t)out_size >= OUT_ELEMS + ATTN_ELEMS);
    float* attn_ptr = attn_in_out ? (out_ptr + OUT_ELEMS) : scratch;

    const int GEMM_SMEM = 2 * GSTAGE * 2;          // bytes: 2 stages * 4 tiles * 2B
    const int SCORE_SMEM = GSTAGE * 2;             // 73728
    cudaFuncSetAttribute(gemm_bf16<0>, cudaFuncAttributeMaxDynamicSharedMemorySize, GEMM_SMEM);
    cudaFuncSetAttribute(gemm_bf16<1>, cudaFuncAttributeMaxDynamicSharedMemorySize, GEMM_SMEM);
    cudaFuncSetAttribute(scores_wmma,  cudaFuncAttributeMaxDynamicSharedMemorySize, SCORE_SMEM);

    // 0) split fp32 -> bf16 hi/lo
    const int NX4 = MTOT * DM / 4, NW4 = DM * DM / 4;
    convert_split<<<NX4 / 256, 256>>>((const float4*)query, (uint2*)xqh, (uint2*)xql, NX4);
    convert_split<<<NX4 / 256, 256>>>((const float4*)key,   (uint2*)xkh, (uint2*)xkl, NX4);
    convert_split<<<NX4 / 256, 256>>>((const float4*)value, (uint2*)xvh, (uint2*)xvl, NX4);
    convert_split<<<NW4 / 256, 256>>>((const float4*)Wq,    (uint2*)wqh, (uint2*)wql, NW4);
    convert_split<<<NW4 / 256, 256>>>((const float4*)Wk,    (uint2*)wkh, (uint2*)wkl, NW4);
    convert_split<<<NW4 / 256, 256>>>((const float4*)Wv,    (uint2*)wvh, (uint2*)wvl, NW4);
    convert_split<<<NW4 / 256, 256>>>((const float4*)Wo,    (uint2*)woh, (uint2*)wol, NW4);

    // 1) QKV projections (q,k -> bf16 hi/lo head layout; v -> fp32 head layout)
    GemmPtrs Pq = {};
    Pq.Ahi[0]=xqh; Pq.Alo[0]=xql; Pq.Whi[0]=wqh; Pq.Wlo[0]=wql; Pq.bias[0]=bq;
    Pq.outHi[0]=qh; Pq.outLo[0]=ql;
    Pq.Ahi[1]=xkh; Pq.Alo[1]=xkl; Pq.Whi[1]=wkh; Pq.Wlo[1]=wkl; Pq.bias[1]=bk;
    Pq.outHi[1]=kh; Pq.outLo[1]=kl;
    Pq.Ahi[2]=xvh; Pq.Alo[2]=xvl; Pq.Whi[2]=wvh; Pq.Wlo[2]=wvl; Pq.bias[2]=bv;
    Pq.outF[2]=vg;
    dim3 gP(DM / 128, MTOT / 128, 3);
    gemm_bf16<0><<<gP, 256, GEMM_SMEM>>>(Pq, MTOT, DM, DM);

    // 2) Scores + harmonic + exp + partial sums (HMMA)
    dim3 gS(SEQ / 128, SEQ / 128, BATCH * NH);
    scores_wmma<<<gS, 256, SCORE_SMEM>>>(qh, ql, kh, kl, reso, phas, attn_ptr, zp);

    // 3) Fused normalize + attn write-back + PV -> ctx bf16 hi/lo
    dim3 gV(SEQ / 128, BATCH * NH);
    pv_fused_kernel<<<gV, 256>>>(attn_ptr, vg, zp, cxh, cxl);

    // 4) Output projection -> d_out
    GemmPtrs Po = {};
    Po.Ahi[0]=cxh; Po.Alo[0]=cxl; Po.Whi[0]=woh; Po.Wlo[0]=wol; Po.bias[0]=bo;
    Po.outF[0]=out_ptr;
    dim3 gO(DM / 128, MTOT / 128, 1);
    gemm_bf16<1><<<gO, 256, GEMM_SMEM>>>(Po, MTOT, DM, DM);
}

// round 6
// speedup vs baseline: 1.7865x; 1.0596x over previous
#include <cuda_runtime.h>
#include <cuda_bf16.h>
#include <mma.h>
#include <math.h>
#include <stdint.h>

using namespace nvcuda;

// Problem constants
#define BATCH 2
#define SEQ   2048
#define DM    1024
#define NH    16
#define HD    64
#define MTOT  (BATCH*SEQ)   // 4096
#define JT    (SEQ/128)     // 16 j-tiles
#define KC    64            // gemm k-chunk
#define LDK   72            // smem bf16 row stride (64 + 8 pad)
#define STG_LD 136          // scores fp32 staging stride

static const size_t OUT_ELEMS  = (size_t)BATCH * SEQ * DM;
static const size_t ATTN_ELEMS = (size_t)BATCH * NH * SEQ * SEQ;

// ---------------------------------------------------------------------------
// Device scratch
// ---------------------------------------------------------------------------
__device__ __nv_bfloat16 g_xq_hi[MTOT*DM], g_xq_lo[MTOT*DM];
__device__ __nv_bfloat16 g_xk_hi[MTOT*DM], g_xk_lo[MTOT*DM];
__device__ __nv_bfloat16 g_xv_hi[MTOT*DM], g_xv_lo[MTOT*DM];
__device__ __nv_bfloat16 g_wq_hi[DM*DM], g_wq_lo[DM*DM];
__device__ __nv_bfloat16 g_wk_hi[DM*DM], g_wk_lo[DM*DM];
__device__ __nv_bfloat16 g_wv_hi[DM*DM], g_wv_lo[DM*DM];
__device__ __nv_bfloat16 g_wo_hi[DM*DM], g_wo_lo[DM*DM];
__device__ __nv_bfloat16 g_q_hi[BATCH*NH*SEQ*HD], g_q_lo[BATCH*NH*SEQ*HD];
__device__ __nv_bfloat16 g_k_hi[BATCH*NH*SEQ*HD], g_k_lo[BATCH*NH*SEQ*HD];
__device__ __nv_bfloat16 g_v_hi[BATCH*NH*SEQ*HD], g_v_lo[BATCH*NH*SEQ*HD];
__device__ __nv_bfloat16 g_ctx_hi[MTOT*DM], g_ctx_lo[MTOT*DM];
__device__ float g_zpart[(size_t)BATCH*NH*JT*SEQ];
__device__ float g_attn_scratch[(size_t)BATCH*NH*SEQ*SEQ];

// ---------------------------------------------------------------------------
// Helpers
// ---------------------------------------------------------------------------
__device__ __forceinline__ void cp16(void* dst, const void* src) {
    asm volatile("cp.async.cg.shared.global [%0], [%1], 16;"
                 :: "r"((uint32_t)__cvta_generic_to_shared(dst)), "l"(src));
}
__device__ __forceinline__ void cp_commit() {
    asm volatile("cp.async.commit_group;");
}
__device__ __forceinline__ uint32_t bfpack(float a, float b) {
    __nv_bfloat162 t(__float2bfloat16(a), __float2bfloat16(b));
    return *(uint32_t*)&t;
}

// fp32 -> bf16 hi/lo split (streaming)
__global__ void __launch_bounds__(256)
convert_split(const float4* __restrict__ src, uint2* __restrict__ hi,
              uint2* __restrict__ lo, int n4)
{
    int i = blockIdx.x * 256 + threadIdx.x;
    if (i >= n4) return;
    float4 v = src[i];
    __nv_bfloat16 hx = __float2bfloat16(v.x), hy = __float2bfloat16(v.y);
    __nv_bfloat16 hz = __float2bfloat16(v.z), hw = __float2bfloat16(v.w);
    __nv_bfloat162 h01(hx, hy), h23(hz, hw);
    hi[i] = make_uint2(*(uint32_t*)&h01, *(uint32_t*)&h23);
    lo[i] = make_uint2(bfpack(v.x - __bfloat162float(hx), v.y - __bfloat162float(hy)),
                       bfpack(v.z - __bfloat162float(hz), v.w - __bfloat162float(hw)));
}

// ---------------------------------------------------------------------------
// HMMA GEMM, pre-split bf16 hi/lo inputs, cp.async double-buffered.
// ---------------------------------------------------------------------------
struct GemmPtrs {
    const __nv_bfloat16 *Ahi[3], *Alo[3], *Whi[3], *Wlo[3];
    const float* bias[3];
    float* outF[3];
    __nv_bfloat16 *outHi[3], *outLo[3];
};

#define GTILE (128*LDK)
#define GSTAGE (4*GTILE)

template<int MODE>
__global__ void __launch_bounds__(256)
gemm_bf16(GemmPtrs P, int M, int N, int K)
{
    extern __shared__ __align__(16) __nv_bfloat16 sm[];
    const int z = (MODE == 0) ? blockIdx.z : 0;
    const __nv_bfloat16* Ahi = P.Ahi[z];
    const __nv_bfloat16* Alo = P.Alo[z];
    const __nv_bfloat16* Whi = P.Whi[z];
    const __nv_bfloat16* Wlo = P.Wlo[z];
    const float* bias = P.bias[z];

    const int tid = threadIdx.x;
    const int wid = tid >> 5;
    const int lane = tid & 31;
    const int wr = wid & 3;
    const int wc = wid >> 2;
    const int m0 = blockIdx.y * 128;
    const int n0 = blockIdx.x * 128;

    wmma::fragment<wmma::accumulator, 16, 16, 16, float> acc[2][4];
#pragma unroll
    for (int i = 0; i < 2; i++)
#pragma unroll
        for (int j = 0; j < 4; j++) wmma::fill_fragment(acc[i][j], 0.f);

    const int NC = K / KC;

    auto stage_copy = [&](int c, int s) {
        const int k0 = c * KC;
        __nv_bfloat16* base = sm + s * GSTAGE;
#pragma unroll
        for (int t = 0; t < 4; t++) {
            int chunk = tid + t * 256;
            int row  = chunk >> 3;
            int coff = (chunk & 7) * 8;
            cp16(base + 0*GTILE + row * LDK + coff, Ahi + (size_t)(m0 + row) * K + k0 + coff);
            cp16(base + 1*GTILE + row * LDK + coff, Alo + (size_t)(m0 + row) * K + k0 + coff);
            cp16(base + 2*GTILE + row * LDK + coff, Whi + (size_t)(n0 + row) * K + k0 + coff);
            cp16(base + 3*GTILE + row * LDK + coff, Wlo + (size_t)(n0 + row) * K + k0 + coff);
        }
        cp_commit();
    };

    stage_copy(0, 0);

    for (int c = 0; c < NC; c++) {
        if (c + 1 < NC) stage_copy(c + 1, (c + 1) & 1);
        if (c + 1 < NC) asm volatile("cp.async.wait_group 1;");
        else            asm volatile("cp.async.wait_group 0;");
        __syncthreads();

        const __nv_bfloat16* base = sm + (c & 1) * GSTAGE;
        const __nv_bfloat16* sAhi = base + 0*GTILE;
        const __nv_bfloat16* sAlo = base + 1*GTILE;
        const __nv_bfloat16* sWhi = base + 2*GTILE;
        const __nv_bfloat16* sWlo = base + 3*GTILE;

#pragma unroll
        for (int kk = 0; kk < KC; kk += 16) {
            wmma::fragment<wmma::matrix_a, 16, 16, 16, __nv_bfloat16, wmma::row_major> aHi[2], aLo[2];
            wmma::fragment<wmma::matrix_b, 16, 16, 16, __nv_bfloat16, wmma::col_major> bHi[4], bLo[4];
#pragma unroll
            for (int i = 0; i < 2; i++) {
                wmma::load_matrix_sync(aHi[i], &sAhi[(wr * 32 + i * 16) * LDK + kk], LDK);
                wmma::load_matrix_sync(aLo[i], &sAlo[(wr * 32 + i * 16) * LDK + kk], LDK);
            }
#pragma unroll
            for (int j = 0; j < 4; j++) {
                wmma::load_matrix_sync(bHi[j], &sWhi[(wc * 64 + j * 16) * LDK + kk], LDK);
                wmma::load_matrix_sync(bLo[j], &sWlo[(wc * 64 + j * 16) * LDK + kk], LDK);
            }
#pragma unroll
            for (int i = 0; i < 2; i++)
#pragma unroll
                for (int j = 0; j < 4; j++) {
                    wmma::mma_sync(acc[i][j], aHi[i], bHi[j], acc[i][j]);
                    wmma::mma_sync(acc[i][j], aHi[i], bLo[j], acc[i][j]);
                    wmma::mma_sync(acc[i][j], aLo[i], bHi[j], acc[i][j]);
                }
        }
        __syncthreads();
    }

    float* scratch = (float*)sm;
    float* ws = scratch + wid * 16 * 20;
    const int er = lane >> 1;
    const int ec = (lane & 1) * 8;

#pragma unroll
    for (int i = 0; i < 2; i++)
#pragma unroll
        for (int j = 0; j < 4; j++) {
            wmma::store_matrix_sync(ws, acc[i][j], 20, wmma::mem_row_major);
            __syncwarp();
            int grow = m0 + wr * 32 + i * 16 + er;
            int col  = n0 + wc * 64 + j * 16 + ec;
            float4 b0 = *(const float4*)&bias[col];
            float4 b1 = *(const float4*)&bias[col + 4];
            float vv[8];
#pragma unroll
            for (int e = 0; e < 4; e++) vv[e]     = ws[er * 20 + ec + e]     + (&b0.x)[e];
#pragma unroll
            for (int e = 0; e < 4; e++) vv[e + 4] = ws[er * 20 + ec + 4 + e] + (&b1.x)[e];

            if (MODE == 0) {
                int b  = grow >> 11;
                int s  = grow & (SEQ - 1);
                int hh = col >> 6;
                int dd = col & (HD - 1);
                size_t off = (((size_t)(b * NH + hh)) * SEQ + s) * HD + dd;
                if (P.outHi[z]) {
                    uint4 uh, ul;
                    __nv_bfloat16 h[8];
#pragma unroll
                    for (int e = 0; e < 8; e++) h[e] = __float2bfloat16(vv[e]);
                    __nv_bfloat162 p0(h[0],h[1]), p1(h[2],h[3]), p2(h[4],h[5]), p3(h[6],h[7]);
                    uh = make_uint4(*(uint32_t*)&p0, *(uint32_t*)&p1, *(uint32_t*)&p2, *(uint32_t*)&p3);
                    ul.x = bfpack(vv[0]-__bfloat162float(h[0]), vv[1]-__bfloat162float(h[1]));
                    ul.y = bfpack(vv[2]-__bfloat162float(h[2]), vv[3]-__bfloat162float(h[3]));
                    ul.z = bfpack(vv[4]-__bfloat162float(h[4]), vv[5]-__bfloat162float(h[5]));
                    ul.w = bfpack(vv[6]-__bfloat162float(h[6]), vv[7]-__bfloat162float(h[7]));
                    *(uint4*)&P.outHi[z][off] = uh;
                    *(uint4*)&P.outLo[z][off] = ul;
                } else {
                    float* dst = &P.outF[z][off];
                    *(float4*)dst       = make_float4(vv[0], vv[1], vv[2], vv[3]);
                    *(float4*)(dst + 4) = make_float4(vv[4], vv[5], vv[6], vv[7]);
                }
            } else {
                float* dst = &P.outF[0][(size_t)grow * N + col];
                *(float4*)dst       = make_float4(vv[0], vv[1], vv[2], vv[3]);
                *(float4*)(dst + 4) = make_float4(vv[4], vv[5], vv[6], vv[7]);
            }
            __syncwarp();
        }
}

// ---------------------------------------------------------------------------
// Scores on HMMA (unchanged from R5)
// ---------------------------------------------------------------------------
__global__ void __launch_bounds__(256)
scores_wmma(const __nv_bfloat16* __restrict__ qhi, const __nv_bfloat16* __restrict__ qlo,
            const __nv_bfloat16* __restrict__ khi, const __nv_bfloat16* __restrict__ klo,
            const float* __restrict__ res, const float* __restrict__ ph,
            float* __restrict__ attn, float* __restrict__ zpart)
{
    extern __shared__ __align__(16) __nv_bfloat16 sm2[];
    __nv_bfloat16* sQhi = sm2 + 0*GTILE;
    __nv_bfloat16* sQlo = sm2 + 1*GTILE;
    __nv_bfloat16* sKhi = sm2 + 2*GTILE;
    __nv_bfloat16* sKlo = sm2 + 3*GTILE;
    float* stage = (float*)sm2;

    const int bh = blockIdx.z;
    const int h  = bh & (NH - 1);
    const int i0 = blockIdx.y * 128;
    const int j0 = blockIdx.x * 128;
    const int tid = threadIdx.x;
    const int wid = tid >> 5;
    const int wr = wid & 3;
    const int wc = wid >> 2;

    const size_t qbase = (size_t)bh * SEQ * HD;

#pragma unroll
    for (int t = 0; t < 4; t++) {
        int chunk = tid + t * 256;
        int row  = chunk >> 3;
        int coff = (chunk & 7) * 8;
        cp16(sQhi + row * LDK + coff, qhi + qbase + (size_t)(i0 + row) * HD + coff);
        cp16(sQlo + row * LDK + coff, qlo + qbase + (size_t)(i0 + row) * HD + coff);
        cp16(sKhi + row * LDK + coff, khi + qbase + (size_t)(j0 + row) * HD + coff);
        cp16(sKlo + row * LDK + coff, klo + qbase + (size_t)(j0 + row) * HD + coff);
    }
    cp_commit();
    asm volatile("cp.async.wait_group 0;");
    __syncthreads();

    wmma::fragment<wmma::accumulator, 16, 16, 16, float> acc[2][4];
#pragma unroll
    for (int i = 0; i < 2; i++)
#pragma unroll
        for (int j = 0; j < 4; j++) wmma::fill_fragment(acc[i][j], 0.f);

#pragma unroll
    for (int kk = 0; kk < 64; kk += 16) {
        wmma::fragment<wmma::matrix_a, 16, 16, 16, __nv_bfloat16, wmma::row_major> aHi[2], aLo[2];
        wmma::fragment<wmma::matrix_b, 16, 16, 16, __nv_bfloat16, wmma::col_major> bHi[4], bLo[4];
#pragma unroll
        for (int i = 0; i < 2; i++) {
            wmma::load_matrix_sync(aHi[i], &sQhi[(wr * 32 + i * 16) * LDK + kk], LDK);
            wmma::load_matrix_sync(aLo[i], &sQlo[(wr * 32 + i * 16) * LDK + kk], LDK);
        }
#pragma unroll
        for (int j = 0; j < 4; j++) {
            wmma::load_matrix_sync(bHi[j], &sKhi[(wc * 64 + j * 16) * LDK + kk], LDK);
            wmma::load_matrix_sync(bLo[j], &sKlo[(wc * 64 + j * 16) * LDK + kk], LDK);
        }
#pragma unroll
        for (int i = 0; i < 2; i++)
#pragma unroll
            for (int j = 0; j < 4; j++) {
                wmma::mma_sync(acc[i][j], aHi[i], bHi[j], acc[i][j]);
                wmma::mma_sync(acc[i][j], aHi[i], bLo[j], acc[i][j]);
                wmma::mma_sync(acc[i][j], aLo[i], bHi[j], acc[i][j]);
            }
    }

    const float R = res[h];
    const float Pp = ph[h];
#pragma unroll
    for (int i = 0; i < 2; i++)
#pragma unroll
        for (int j = 0; j < 4; j++)
#pragma unroll
            for (int e = 0; e < acc[i][j].num_elements; e++) {
                float s = acc[i][j].x[e] * 0.125f;
                s += R * __sinf(s + Pp);
                acc[i][j].x[e] = __expf(s);
            }

    __syncthreads();
#pragma unroll
    for (int i = 0; i < 2; i++)
#pragma unroll
        for (int j = 0; j < 4; j++)
            wmma::store_matrix_sync(&stage[(size_t)(wr * 32 + i * 16) * STG_LD + wc * 64 + j * 16],
                                    acc[i][j], STG_LD, wmma::mem_row_major);
    __syncthreads();

    {
        int row  = tid >> 1;
        int base = (tid & 1) * 64;
        float s = 0.f;
        const float* pr = &stage[(size_t)row * STG_LD + base];
#pragma unroll
        for (int e = 0; e < 64; e += 4) {
            float4 v4 = *(const float4*)&pr[e];
            s += v4.x + v4.y + v4.z + v4.w;
        }
        s += __shfl_xor_sync(0xffffffffu, s, 1);
        if ((tid & 1) == 0)
            zpart[((size_t)bh * JT + blockIdx.x) * SEQ + i0 + row] = s;
    }

#pragma unroll
    for (int t = 0; t < 16; t++) {
        int idx = tid + t * 256;
        int row = idx >> 5;
        int c4  = (idx & 31) * 4;
        float4 v4 = *(const float4*)&stage[(size_t)row * STG_LD + c4];
        *(float4*)&attn[((size_t)bh * SEQ + i0 + row) * SEQ + j0 + c4] = v4;
    }
}

// ---------------------------------------------------------------------------
// PV on HMMA bf16x3: normalize attn in place + P@V with tensor cores.
// P: read exp, *invZ, write back (attn output), convert hi/lo -> smem.
// V: pre-split bf16 hi/lo, cp.async.
// CTA: 128 rows x 64 cols (full head dim), 8 warps 4x2, warp 32x32, acc 2x2.
// ---------------------------------------------------------------------------
#define PV_SMEM ((2*128*LDK + 2*64*LDK) * 2)   // bytes = 55296

__global__ void __launch_bounds__(256)
pv_wmma(float* __restrict__ attn,
        const __nv_bfloat16* __restrict__ vhi, const __nv_bfloat16* __restrict__ vlo,
        const float* __restrict__ zpart,
        __nv_bfloat16* __restrict__ ctxhi, __nv_bfloat16* __restrict__ ctxlo)
{
    extern __shared__ __align__(16) __nv_bfloat16 smp[];
    __nv_bfloat16* sPhi = smp;
    __nv_bfloat16* sPlo = smp + 128*LDK;
    __nv_bfloat16* sVhi = smp + 2*128*LDK;
    __nv_bfloat16* sVlo = smp + 2*128*LDK + 64*LDK;
    __shared__ float invZ[128];

    const int bh = blockIdx.y;
    const int b  = bh >> 4;
    const int h  = bh & 15;
    const int i0 = blockIdx.x * 128;
    const int tid = threadIdx.x;
    const int wid = tid >> 5;
    const int lane = tid & 31;
    const int wr = wid & 3;     // 4 row groups x 32
    const int wc = wid >> 2;    // 2 col groups x 32

    if (tid < 128) {
        float z = 0.f;
#pragma unroll
        for (int jt = 0; jt < JT; jt++)
            z += zpart[((size_t)bh * JT + jt) * SEQ + i0 + tid];
        invZ[tid] = 1.f / z;
    }
    __syncthreads();

    float* Pb = attn + ((size_t)bh * SEQ + i0) * SEQ;
    const __nv_bfloat16* Vbh = vhi + (size_t)bh * SEQ * HD;
    const __nv_bfloat16* Vbl = vlo + (size_t)bh * SEQ * HD;

    wmma::fragment<wmma::accumulator, 16, 16, 16, float> acc[2][2];
#pragma unroll
    for (int i = 0; i < 2; i++)
#pragma unroll
        for (int j = 0; j < 2; j++) wmma::fill_fragment(acc[i][j], 0.f);

    for (int k0 = 0; k0 < SEQ; k0 += 64) {
        // V tiles via cp.async (64 rows x 64 bf16 = 8 cp16 per row)
#pragma unroll
        for (int t = 0; t < 2; t++) {
            int slot = tid + t * 256;      // 0..511
            int row  = slot >> 3;
            int co   = (slot & 7) * 8;
            cp16(sVhi + row * LDK + co, Vbh + (size_t)(k0 + row) * HD + co);
            cp16(sVlo + row * LDK + co, Vbl + (size_t)(k0 + row) * HD + co);
        }
        cp_commit();

        // P tile: load fp32 exp, normalize, write back, split to hi/lo smem
#pragma unroll
        for (int t = 0; t < 8; t++) {
            int slot = tid + t * 256;      // 0..2047
            int row  = slot >> 4;
            int c4   = (slot & 15) * 4;
            float iz = invZ[row];
            float4 e = *(const float4*)&Pb[(size_t)row * SEQ + k0 + c4];
            float4 p = {e.x * iz, e.y * iz, e.z * iz, e.w * iz};
            *(float4*)&Pb[(size_t)row * SEQ + k0 + c4] = p;
            __nv_bfloat16 h0 = __float2bfloat16(p.x), h1 = __float2bfloat16(p.y);
            __nv_bfloat16 h2 = __float2bfloat16(p.z), h3 = __float2bfloat16(p.w);
            __nv_bfloat162 q0(h0, h1), q1(h2, h3);
            *(uint2*)&sPhi[row * LDK + c4] = make_uint2(*(uint32_t*)&q0, *(uint32_t*)&q1);
            *(uint2*)&sPlo[row * LDK + c4] =
                make_uint2(bfpack(p.x - __bfloat162float(h0), p.y - __bfloat162float(h1)),
                           bfpack(p.z - __bfloat162float(h2), p.w - __bfloat162float(h3)));
        }
        asm volatile("cp.async.wait_group 0;");
        __syncthreads();

#pragma unroll
        for (int kk = 0; kk < 64; kk += 16) {
            wmma::fragment<wmma::matrix_a, 16, 16, 16, __nv_bfloat16, wmma::row_major> aHi[2], aLo[2];
            wmma::fragment<wmma::matrix_b, 16, 16, 16, __nv_bfloat16, wmma::row_major> bHi[2], bLo[2];
#pragma unroll
            for (int i = 0; i < 2; i++) {
                wmma::load_matrix_sync(aHi[i], &sPhi[(wr * 32 + i * 16) * LDK + kk], LDK);
                wmma::load_matrix_sync(aLo[i], &sPlo[(wr * 32 + i * 16) * LDK + kk], LDK);
            }
#pragma unroll
            for (int j = 0; j < 2; j++) {
                wmma::load_matrix_sync(bHi[j], &sVhi[kk * LDK + wc * 32 + j * 16], LDK);
                wmma::load_matrix_sync(bLo[j], &sVlo[kk * LDK + wc * 32 + j * 16], LDK);
            }
#pragma unroll
            for (int i = 0; i < 2; i++)
#pragma unroll
                for (int j = 0; j < 2; j++) {
                    wmma::mma_sync(acc[i][j], aHi[i], bHi[j], acc[i][j]);
                    wmma::mma_sync(acc[i][j], aHi[i], bLo[j], acc[i][j]);
                    wmma::mma_sync(acc[i][j], aLo[i], bHi[j], acc[i][j]);
                }
        }
        __syncthreads();
    }

    // Epilogue: stage, convert to ctx hi/lo
    float* scratch = (float*)smp;
    float* ws = scratch + wid * 16 * 20;
    const int er = lane >> 1;
    const int ec = (lane & 1) * 8;

#pragma unroll
    for (int i = 0; i < 2; i++)
#pragma unroll
        for (int j = 0; j < 2; j++) {
            wmma::store_matrix_sync(ws, acc[i][j], 20, wmma::mem_row_major);
            __syncwarp();
            int row = i0 + wr * 32 + i * 16 + er;
            int col = wc * 32 + j * 16 + ec;
            size_t off = ((size_t)b * SEQ + row) * DM + h * HD + col;
            float vv[8];
#pragma unroll
            for (int e = 0; e < 8; e++) vv[e] = ws[er * 20 + ec + e];
            __nv_bfloat16 hh[8];
#pragma unroll
            for (int e = 0; e < 8; e++) hh[e] = __float2bfloat16(vv[e]);
            __nv_bfloat162 p0(hh[0],hh[1]), p1(hh[2],hh[3]), p2(hh[4],hh[5]), p3(hh[6],hh[7]);
            *(uint4*)&ctxhi[off] = make_uint4(*(uint32_t*)&p0, *(uint32_t*)&p1,
                                              *(uint32_t*)&p2, *(uint32_t*)&p3);
            uint4 ul;
            ul.x = bfpack(vv[0]-__bfloat162float(hh[0]), vv[1]-__bfloat162float(hh[1]));
            ul.y = bfpack(vv[2]-__bfloat162float(hh[2]), vv[3]-__bfloat162float(hh[3]));
            ul.z = bfpack(vv[4]-__bfloat162float(hh[4]), vv[5]-__bfloat162float(hh[5]));
            ul.w = bfpack(vv[6]-__bfloat162float(hh[6]), vv[7]-__bfloat162float(hh[7]));
            *(uint4*)&ctxlo[off] = ul;
            __syncwarp();
        }
}

// ---------------------------------------------------------------------------
// Launch
// ---------------------------------------------------------------------------
extern "C" void kernel_launch(void* const* d_in, const int* in_sizes, int n_in,
                              void* d_out, int out_size)
{
    const float* query = (const float*)d_in[0];
    const float* key   = (const float*)d_in[1];
    const float* value = (const float*)d_in[2];
    const float* Wq    = (const float*)d_in[3];
    const float* bq    = (const float*)d_in[4];
    const float* Wk    = (const float*)d_in[5];
    const float* bk    = (const float*)d_in[6];
    const float* Wv    = (const float*)d_in[7];
    const float* bv    = (const float*)d_in[8];
    const float* Wo    = (const float*)d_in[9];
    const float* bo    = (const float*)d_in[10];
    const float* reso  = (const float*)d_in[11];
    const float* phas  = (const float*)d_in[12];

    __nv_bfloat16 *xqh,*xql,*xkh,*xkl,*xvh,*xvl, *wqh,*wql,*wkh,*wkl,*wvh,*wvl,*woh,*wol;
    __nv_bfloat16 *qh,*ql,*kh,*kl,*vh,*vl, *cxh,*cxl;
    float *zp, *scratch;
    cudaGetSymbolAddress((void**)&xqh, g_xq_hi); cudaGetSymbolAddress((void**)&xql, g_xq_lo);
    cudaGetSymbolAddress((void**)&xkh, g_xk_hi); cudaGetSymbolAddress((void**)&xkl, g_xk_lo);
    cudaGetSymbolAddress((void**)&xvh, g_xv_hi); cudaGetSymbolAddress((void**)&xvl, g_xv_lo);
    cudaGetSymbolAddress((void**)&wqh, g_wq_hi); cudaGetSymbolAddress((void**)&wql, g_wq_lo);
    cudaGetSymbolAddress((void**)&wkh, g_wk_hi); cudaGetSymbolAddress((void**)&wkl, g_wk_lo);
    cudaGetSymbolAddress((void**)&wvh, g_wv_hi); cudaGetSymbolAddress((void**)&wvl, g_wv_lo);
    cudaGetSymbolAddress((void**)&woh, g_wo_hi); cudaGetSymbolAddress((void**)&wol, g_wo_lo);
    cudaGetSymbolAddress((void**)&qh,  g_q_hi);  cudaGetSymbolAddress((void**)&ql,  g_q_lo);
    cudaGetSymbolAddress((void**)&kh,  g_k_hi);  cudaGetSymbolAddress((void**)&kl,  g_k_lo);
    cudaGetSymbolAddress((void**)&vh,  g_v_hi);  cudaGetSymbolAddress((void**)&vl,  g_v_lo);
    cudaGetSymbolAddress((void**)&cxh, g_ctx_hi); cudaGetSymbolAddress((void**)&cxl, g_ctx_lo);
    cudaGetSymbolAddress((void**)&zp,  g_zpart);
    cudaGetSymbolAddress((void**)&scratch, g_attn_scratch);

    float* out_ptr = (float*)d_out;
    const bool attn_in_out = ((size_t)out_size >= OUT_ELEMS + ATTN_ELEMS);
    float* attn_ptr = attn_in_out ? (out_ptr + OUT_ELEMS) : scratch;

    const int GEMM_SMEM = 2 * GSTAGE * 2;
    const int SCORE_SMEM = GSTAGE * 2;
    cudaFuncSetAttribute(gemm_bf16<0>, cudaFuncAttributeMaxDynamicSharedMemorySize, GEMM_SMEM);
    cudaFuncSetAttribute(gemm_bf16<1>, cudaFuncAttributeMaxDynamicSharedMemorySize, GEMM_SMEM);
    cudaFuncSetAttribute(scores_wmma,  cudaFuncAttributeMaxDynamicSharedMemorySize, SCORE_SMEM);
    cudaFuncSetAttribute(pv_wmma,      cudaFuncAttributeMaxDynamicSharedMemorySize, PV_SMEM);

    // 0) split fp32 -> bf16 hi/lo
    const int NX4 = MTOT * DM / 4, NW4 = DM * DM / 4;
    convert_split<<<NX4 / 256, 256>>>((const float4*)query, (uint2*)xqh, (uint2*)xql, NX4);
    convert_split<<<NX4 / 256, 256>>>((const float4*)key,   (uint2*)xkh, (uint2*)xkl, NX4);
    convert_split<<<NX4 / 256, 256>>>((const float4*)value, (uint2*)xvh, (uint2*)xvl, NX4);
    convert_split<<<NW4 / 256, 256>>>((const float4*)Wq,    (uint2*)wqh, (uint2*)wql, NW4);
    convert_split<<<NW4 / 256, 256>>>((const float4*)Wk,    (uint2*)wkh, (uint2*)wkl, NW4);
    convert_split<<<NW4 / 256, 256>>>((const float4*)Wv,    (uint2*)wvh, (uint2*)wvl, NW4);
    convert_split<<<NW4 / 256, 256>>>((const float4*)Wo,    (uint2*)woh, (uint2*)wol, NW4);

    // 1) QKV projections -> all bf16 hi/lo head layout
    GemmPtrs Pq = {};
    Pq.Ahi[0]=xqh; Pq.Alo[0]=xql; Pq.Whi[0]=wqh; Pq.Wlo[0]=wql; Pq.bias[0]=bq;
    Pq.outHi[0]=qh; Pq.outLo[0]=ql;
    Pq.Ahi[1]=xkh; Pq.Alo[1]=xkl; Pq.Whi[1]=wkh; Pq.Wlo[1]=wkl; Pq.bias[1]=bk;
    Pq.outHi[1]=kh; Pq.outLo[1]=kl;
    Pq.Ahi[2]=xvh; Pq.Alo[2]=xvl; Pq.Whi[2]=wvh; Pq.Wlo[2]=wvl; Pq.bias[2]=bv;
    Pq.outHi[2]=vh; Pq.outLo[2]=vl;
    dim3 gP(DM / 128, MTOT / 128, 3);
    gemm_bf16<0><<<gP, 256, GEMM_SMEM>>>(Pq, MTOT, DM, DM);

    // 2) Scores + harmonic + exp + partial sums (HMMA)
    dim3 gS(SEQ / 128, SEQ / 128, BATCH * NH);
    scores_wmma<<<gS, 256, SCORE_SMEM>>>(qh, ql, kh, kl, reso, phas, attn_ptr, zp);

    // 3) Normalize + PV on HMMA -> ctx bf16 hi/lo
    dim3 gV(SEQ / 128, BATCH * NH);
    pv_wmma<<<gV, 256, PV_SMEM>>>(attn_ptr, vh, vl, zp, cxh, cxl);

    // 4) Output projection -> d_out
    GemmPtrs Po = {};
    Po.Ahi[0]=cxh; Po.Alo[0]=cxl; Po.Whi[0]=woh; Po.Wlo[0]=wol; Po.bias[0]=bo;
    Po.outF[0]=out_ptr;
    dim3 gO(DM / 128, MTOT / 128, 1);
    gemm_bf16<1><<<gO, 256, GEMM_SMEM>>>(Po, MTOT, DM, DM);
}